// round 4
// baseline (speedup 1.0000x reference)
#include <cuda_runtime.h>
#include <cstdint>

// Problem constants
#define BATCH 4
#define DIN   128
#define HIN   192
#define WIN   192
#define OH    182
#define OW    182
#define N_OUT 15634528.0     // 4*118*182*182

// Tile config
#define TY 16
#define TX 16
#define SH 26        // TY + 10
#define SWP 48       // padded slab row stride (floats); cols 0..27 used
#define GX 12        // ceil(182/16)
#define GY 12
#define NBLK (GX * GY * BATCH)   // 576

// Gaussian(sigma=1.5, K=11). constexpr + static indexing => FFMA-imm.
__device__ constexpr float WG[11] = {
    0.00102834f, 0.00759875f, 0.03600077f, 0.10936078f, 0.21300553f,
    0.26601172f,
    0.21300553f, 0.10936078f, 0.03600077f, 0.00759875f, 0.00102834f
};

__device__ float g_part[NBLK];

// ---------------------------------------------------------------------------
// Fully fused SSIM3D: W-conv, H-conv, per-thread register D-ring, SSIM, reduce.
// Block = 256 threads = 16x16 output tile for one (b, x-tile, y-tile).
// ---------------------------------------------------------------------------
__global__ __launch_bounds__(256)
void k_fused(const float* __restrict__ img1, const float* __restrict__ img2) {
    __shared__ float sa[SH][SWP];
    __shared__ float sb[SH][SWP];
    __shared__ float wt[5][SH][TX];
    __shared__ float wred[8];

    const int b  = blockIdx.z;
    const int y0 = blockIdx.y * TY;
    const int x0 = blockIdx.x * TX;
    const int t  = threadIdx.x;
    const int tx = t & 15;
    const int ty = t >> 4;
    const bool act = (x0 + tx < OW) && (y0 + ty < OH);

    const float* p1 = img1 + (size_t)b * (DIN * HIN * WIN);
    const float* p2 = img2 + (size_t)b * (DIN * HIN * WIN);

    // W-pass task mapping (104 tasks: 26 rows x 4 segments of 4 outputs)
    const int wrow = t >> 2;
    const int wxs  = (t & 3) * 4;

    // Per-thread D-direction ring: 5 fields x 11 depth slices, in registers.
    float h0[11], h1[11], h2[11], h3[11], h4[11];
    float acc = 0.f;

#pragma unroll 1
    for (int d = 0; d < DIN; d++) {
        // ---- Phase A: load input slab (2 fields x 26 rows x 7 float4) ----
        {
            const float* q1 = p1 + (size_t)d * (HIN * WIN);
            const float* q2 = p2 + (size_t)d * (HIN * WIN);
            for (int i = t; i < 2 * SH * 7; i += 256) {
                int fld = i / (SH * 7);
                int s   = i - fld * (SH * 7);
                int r   = s / 7;
                int c   = s - r * 7;
                int gy  = y0 + r;     if (gy > HIN - 1) gy = HIN - 1;
                int gx  = x0 + 4 * c; if (gx > WIN - 4) gx = WIN - 4;
                float4 v = *reinterpret_cast<const float4*>(
                    (fld ? q2 : q1) + gy * WIN + gx);
                float (*dst)[SWP] = fld ? sb : sa;
                *reinterpret_cast<float4*>(&dst[r][4 * c]) = v;
            }
        }
        __syncthreads();

        // ---- Phase B: W-direction conv over 5 fields (sliding window) ----
        if (t < SH * 4) {
            float a[16], e[16];
#pragma unroll
            for (int c = 0; c < 4; c++) {
                float4 va = *reinterpret_cast<const float4*>(&sa[wrow][wxs + 4 * c]);
                float4 ve = *reinterpret_cast<const float4*>(&sb[wrow][wxs + 4 * c]);
                a[4*c+0] = va.x; a[4*c+1] = va.y; a[4*c+2] = va.z; a[4*c+3] = va.w;
                e[4*c+0] = ve.x; e[4*c+1] = ve.y; e[4*c+2] = ve.z; e[4*c+3] = ve.w;
            }
            float m1[4]  = {0,0,0,0}, m2[4]  = {0,0,0,0};
            float s11[4] = {0,0,0,0}, s22[4] = {0,0,0,0}, s12[4] = {0,0,0,0};
#pragma unroll
            for (int p = 0; p < 14; p++) {
                float av = a[p], bv = e[p];
                float aa = av * av, bb = bv * bv, ab = av * bv;
#pragma unroll
                for (int j = 0; j < 4; j++) {
                    int k = p - j;
                    if (k >= 0 && k <= 10) {
                        m1[j]  = fmaf(WG[k], av, m1[j]);
                        m2[j]  = fmaf(WG[k], bv, m2[j]);
                        s11[j] = fmaf(WG[k], aa, s11[j]);
                        s22[j] = fmaf(WG[k], bb, s22[j]);
                        s12[j] = fmaf(WG[k], ab, s12[j]);
                    }
                }
            }
            *reinterpret_cast<float4*>(&wt[0][wrow][wxs]) = make_float4(m1[0],  m1[1],  m1[2],  m1[3]);
            *reinterpret_cast<float4*>(&wt[1][wrow][wxs]) = make_float4(m2[0],  m2[1],  m2[2],  m2[3]);
            *reinterpret_cast<float4*>(&wt[2][wrow][wxs]) = make_float4(s11[0], s11[1], s11[2], s11[3]);
            *reinterpret_cast<float4*>(&wt[3][wrow][wxs]) = make_float4(s22[0], s22[1], s22[2], s22[3]);
            *reinterpret_cast<float4*>(&wt[4][wrow][wxs]) = make_float4(s12[0], s12[1], s12[2], s12[3]);
        }
        __syncthreads();

        // ---- Phase C: H-conv -> register ring -> D-conv + SSIM ----
        {
            float n0 = 0.f, n1 = 0.f, n2 = 0.f, n3 = 0.f, n4 = 0.f;
#pragma unroll
            for (int k = 0; k < 11; k++) {
                n0 = fmaf(WG[k], wt[0][ty + k][tx], n0);
                n1 = fmaf(WG[k], wt[1][ty + k][tx], n1);
                n2 = fmaf(WG[k], wt[2][ty + k][tx], n2);
                n3 = fmaf(WG[k], wt[3][ty + k][tx], n3);
                n4 = fmaf(WG[k], wt[4][ty + k][tx], n4);
            }
            // shift ring (all static indices -> registers)
#pragma unroll
            for (int i = 0; i < 10; i++) {
                h0[i] = h0[i+1]; h1[i] = h1[i+1]; h2[i] = h2[i+1];
                h3[i] = h3[i+1]; h4[i] = h4[i+1];
            }
            h0[10] = n0; h1[10] = n1; h2[10] = n2; h3[10] = n3; h4[10] = n4;

            if (d >= 10) {
                float M1 = 0.f, M2 = 0.f, P11 = 0.f, P22 = 0.f, P12 = 0.f;
#pragma unroll
                for (int k = 0; k < 11; k++) {
                    M1  = fmaf(WG[k], h0[k], M1);
                    M2  = fmaf(WG[k], h1[k], M2);
                    P11 = fmaf(WG[k], h2[k], P11);
                    P22 = fmaf(WG[k], h3[k], P22);
                    P12 = fmaf(WG[k], h4[k], P12);
                }
                float mu11 = M1 * M1;
                float mu22 = M2 * M2;
                float mu12 = M1 * M2;
                float sg1  = P11 - mu11;
                float sg2  = P22 - mu22;
                float sg12 = P12 - mu12;
                const float C1 = 1e-4f;   // (0.01*1)^2
                const float C2 = 9e-4f;   // (0.03*1)^2
                float num = (2.f * mu12 + C1) * (2.f * sg12 + C2);
                float den = (mu11 + mu22 + C1) * (sg1 + sg2 + C2);
                if (act) acc += __fdividef(num, den);
            }
        }
        __syncthreads();   // protect wt before next B (A(d+1) is disjoint-safe)
    }

    // ---- block reduction -> per-block partial (no atomics) ----
    float v = acc;
#pragma unroll
    for (int o = 16; o > 0; o >>= 1)
        v += __shfl_down_sync(0xffffffffu, v, o);
    if ((t & 31) == 0) wred[t >> 5] = v;
    __syncthreads();
    if (t == 0) {
        float s = 0.f;
#pragma unroll
        for (int i = 0; i < 8; i++) s += wred[i];
        int bid = blockIdx.x + GX * (blockIdx.y + GY * blockIdx.z);
        g_part[bid] = s;
    }
}

// ---------------------------------------------------------------------------
// Finalize: deterministic double-precision tree over 576 partials.
// ---------------------------------------------------------------------------
__global__ __launch_bounds__(256)
void k_finalize(float* __restrict__ out) {
    __shared__ double sred[256];
    const int t = threadIdx.x;
    double s = 0.0;
    for (int i = t; i < NBLK; i += 256) s += (double)g_part[i];
    sred[t] = s;
    __syncthreads();
    for (int o = 128; o > 0; o >>= 1) {
        if (t < o) sred[t] += sred[t + o];
        __syncthreads();
    }
    if (t == 0) out[0] = (float)(sred[0] / N_OUT);
}

extern "C" void kernel_launch(void* const* d_in, const int* in_sizes, int n_in,
                              void* d_out, int out_size) {
    const float* img1 = (const float*)d_in[0];
    const float* img2 = (const float*)d_in[1];
    float* out = (float*)d_out;

    dim3 grid(GX, GY, BATCH);    // 12 x 12 x 4 = 576 blocks
    k_fused<<<grid, 256>>>(img1, img2);
    k_finalize<<<1, 256>>>(out);
}

// round 5
// speedup vs baseline: 1.2095x; 1.2095x over previous
#include <cuda_runtime.h>
#include <cstdint>

// Problem constants
#define BATCH 4
#define DIN   128
#define HIN   192
#define WIN   192
#define KR    11
#define OH    182
#define OW    182
#define OWP   184                            // padded intermediate row
#define DSTRIDE   (OH * OWP)
#define MIDF      (BATCH * DIN * DSTRIDE)
#define N_OUT     15634528.0                 // 4*118*182*182

// k1 tile
#define TY 22
#define TX 32
#define SR 32        // TY + 10 slab rows
#define SRW 44       // 42 cols padded
#define WTW 36       // wt row stride (padded)
#define GX 6         // ceil(182/32)
#define GY 9         // ceil(182/22)

#define NB2 (BATCH * OH)                     // 728 k2 blocks

// Gaussian(sigma=1.5, K=11). constexpr + static indexing => FFMA-imm.
__device__ constexpr float WG[11] = {
    0.00102834f, 0.00759875f, 0.03600077f, 0.10936078f, 0.21300553f,
    0.26601172f,
    0.21300553f, 0.10936078f, 0.03600077f, 0.00759875f, 0.00102834f
};

// Scratch (~343 MB) + per-block partials. Device globals => allowed.
__device__ float g_mid[5ULL * MIDF];
__device__ float g_part[NB2];

// ---------------------------------------------------------------------------
// Kernel 1: per depth slice, fused separable 2D Gaussian over 5 fields.
// Output tile 22(y) x 32(x). W-pass: 256 tasks (100% util), 4 x-outputs each.
// H-pass: 176 x-quad tasks, vectorized LDS.128/STG.128.
// ---------------------------------------------------------------------------
__global__ __launch_bounds__(256, 2)
void k_conv2d(const float* __restrict__ img1, const float* __restrict__ img2) {
    __shared__ float sa[SR][SRW];
    __shared__ float sb[SR][SRW];
    __shared__ float wt[5][SR][WTW];

    const int bz = blockIdx.z;                 // b*DIN + d
    const int y0 = blockIdx.y * TY;
    const int x0 = blockIdx.x * TX;
    const float* p1 = img1 + (size_t)bz * (HIN * WIN);
    const float* p2 = img2 + (size_t)bz * (HIN * WIN);
    const int t = threadIdx.x;

    // ---- load slab: 2 fields x 32 rows x 11 float4 = 704 loads ----
    for (int i = t; i < 2 * SR * 11; i += 256) {
        int fld = i / (SR * 11);
        int s   = i - fld * (SR * 11);
        int r   = s / 11, c = s - r * 11;
        int gy  = y0 + r;     if (gy > HIN - 1) gy = HIN - 1;
        int gx  = x0 + 4 * c; if (gx > WIN - 4) gx = WIN - 4;
        float4 v = *reinterpret_cast<const float4*>((fld ? p2 : p1) + gy * WIN + gx);
        float (*dst)[SRW] = fld ? sb : sa;
        *reinterpret_cast<float4*>(&dst[r][4 * c]) = v;
    }
    __syncthreads();

    // ---- W pass: 32 rows x 8 quads = 256 tasks, 4 outputs each ----
    {
        const int row = t >> 3;
        const int xs  = (t & 7) * 4;

        float a[16], e[16];
#pragma unroll
        for (int c = 0; c < 4; c++) {
            float4 va = *reinterpret_cast<const float4*>(&sa[row][xs + 4 * c]);
            float4 ve = *reinterpret_cast<const float4*>(&sb[row][xs + 4 * c]);
            a[4*c+0]=va.x; a[4*c+1]=va.y; a[4*c+2]=va.z; a[4*c+3]=va.w;
            e[4*c+0]=ve.x; e[4*c+1]=ve.y; e[4*c+2]=ve.z; e[4*c+3]=ve.w;
        }
        float m1[4]  = {0,0,0,0}, m2[4]  = {0,0,0,0};
        float s11[4] = {0,0,0,0}, s22[4] = {0,0,0,0}, s12[4] = {0,0,0,0};
#pragma unroll
        for (int p = 0; p < 14; p++) {
            float av = a[p], bv = e[p];
            float aa = av * av, bb = bv * bv, ab = av * bv;
#pragma unroll
            for (int j = 0; j < 4; j++) {
                int k = p - j;
                if (k >= 0 && k <= 10) {
                    m1[j]  = fmaf(WG[k], av, m1[j]);
                    m2[j]  = fmaf(WG[k], bv, m2[j]);
                    s11[j] = fmaf(WG[k], aa, s11[j]);
                    s22[j] = fmaf(WG[k], bb, s22[j]);
                    s12[j] = fmaf(WG[k], ab, s12[j]);
                }
            }
        }
        *reinterpret_cast<float4*>(&wt[0][row][xs]) = make_float4(m1[0],  m1[1],  m1[2],  m1[3]);
        *reinterpret_cast<float4*>(&wt[1][row][xs]) = make_float4(m2[0],  m2[1],  m2[2],  m2[3]);
        *reinterpret_cast<float4*>(&wt[2][row][xs]) = make_float4(s11[0], s11[1], s11[2], s11[3]);
        *reinterpret_cast<float4*>(&wt[3][row][xs]) = make_float4(s22[0], s22[1], s22[2], s22[3]);
        *reinterpret_cast<float4*>(&wt[4][row][xs]) = make_float4(s12[0], s12[1], s12[2], s12[3]);
    }
    __syncthreads();

    // ---- H pass: 22 y x 8 x-quads = 176 tasks, 4 x-outputs each ----
    if (t < TY * 8) {
        const int y  = t >> 3;
        const int xs = (t & 7) * 4;

        float acc[5][4];
#pragma unroll
        for (int f = 0; f < 5; f++)
#pragma unroll
            for (int j = 0; j < 4; j++) acc[f][j] = 0.f;

#pragma unroll
        for (int k = 0; k < 11; k++) {
#pragma unroll
            for (int f = 0; f < 5; f++) {
                float4 v = *reinterpret_cast<const float4*>(&wt[f][y + k][xs]);
                acc[f][0] = fmaf(WG[k], v.x, acc[f][0]);
                acc[f][1] = fmaf(WG[k], v.y, acc[f][1]);
                acc[f][2] = fmaf(WG[k], v.z, acc[f][2]);
                acc[f][3] = fmaf(WG[k], v.w, acc[f][3]);
            }
        }

        const int oy = y0 + y;
        const int ox = x0 + xs;
        // ox is a multiple of 4; ox<OW implies ox<=180 -> quad fits row (pad 182,183)
        if (oy < OH && ox < OW) {
            size_t o = (size_t)bz * DSTRIDE + (size_t)oy * OWP + ox;
#pragma unroll
            for (int f = 0; f < 5; f++)
                *reinterpret_cast<float4*>(&g_mid[(size_t)f * MIDF + o]) =
                    make_float4(acc[f][0], acc[f][1], acc[f][2], acc[f][3]);
        }
    }
}

// ---------------------------------------------------------------------------
// Kernel 2: D-conv + SSIM + reduction. One block per (b, y) row; each thread
// owns one w-column; 11x5 history in registers; no barriers in main loop.
// ---------------------------------------------------------------------------
__global__ __launch_bounds__(192)
void k_dssim() {
    __shared__ float wsum[6];

    const int by = blockIdx.x;          // b*OH + y
    const int b  = by / OH;
    const int y  = by - b * OH;
    const int w  = threadIdx.x;         // 0..191
    const bool act = (w < OW);
    const int wl = act ? w : 0;

    const size_t base = ((size_t)(b * DIN) * OH + y) * OWP + wl;

    float h[5][11];
    float part = 0.f;

    for (int i0 = 0; i0 < 132; i0 += 11) {
#pragma unroll
        for (int r = 0; r < 11; r++) {
            const int d = i0 + r;
            if (d < DIN) {
                const size_t off = base + (size_t)d * DSTRIDE;
#pragma unroll
                for (int f = 0; f < 5; f++)
                    h[f][r] = g_mid[(size_t)f * MIDF + off];

                if (d >= 10) {
                    float m1 = 0.f, m2 = 0.f, p11 = 0.f, p22 = 0.f, p12 = 0.f;
#pragma unroll
                    for (int k = 0; k < 11; k++) {
                        const int s = (r + 1 + k) % 11;   // static after unroll
                        m1  = fmaf(WG[k], h[0][s], m1);
                        m2  = fmaf(WG[k], h[1][s], m2);
                        p11 = fmaf(WG[k], h[2][s], p11);
                        p22 = fmaf(WG[k], h[3][s], p22);
                        p12 = fmaf(WG[k], h[4][s], p12);
                    }
                    float mu11 = m1 * m1;
                    float mu22 = m2 * m2;
                    float mu12 = m1 * m2;
                    float sg1  = p11 - mu11;
                    float sg2  = p22 - mu22;
                    float sg12 = p12 - mu12;
                    const float C1 = 1e-4f;
                    const float C2 = 9e-4f;
                    float num = (2.f * mu12 + C1) * (2.f * sg12 + C2);
                    float den = (mu11 + mu22 + C1) * (sg1 + sg2 + C2);
                    if (act) part += __fdividef(num, den);
                }
            }
        }
    }

    float v = part;
#pragma unroll
    for (int o = 16; o > 0; o >>= 1)
        v += __shfl_down_sync(0xffffffffu, v, o);
    if ((threadIdx.x & 31) == 0) wsum[threadIdx.x >> 5] = v;
    __syncthreads();
    if (threadIdx.x == 0) {
        float s = 0.f;
#pragma unroll
        for (int i = 0; i < 6; i++) s += wsum[i];
        g_part[by] = s;
    }
}

// ---------------------------------------------------------------------------
// Finalize: deterministic double tree over 728 partials.
// ---------------------------------------------------------------------------
__global__ __launch_bounds__(256)
void k_finalize(float* __restrict__ out) {
    __shared__ double sred[256];
    const int t = threadIdx.x;
    double s = 0.0;
    for (int i = t; i < NB2; i += 256) s += (double)g_part[i];
    sred[t] = s;
    __syncthreads();
    for (int o = 128; o > 0; o >>= 1) {
        if (t < o) sred[t] += sred[t + o];
        __syncthreads();
    }
    if (t == 0) out[0] = (float)(sred[0] / N_OUT);
}

extern "C" void kernel_launch(void* const* d_in, const int* in_sizes, int n_in,
                              void* d_out, int out_size) {
    const float* img1 = (const float*)d_in[0];
    const float* img2 = (const float*)d_in[1];
    float* out = (float*)d_out;

    dim3 g1(GX, GY, BATCH * DIN);   // 6 x 9 x 512 = 27,648 blocks
    k_conv2d<<<g1, 256>>>(img1, img2);
    k_dssim<<<NB2, 192>>>();
    k_finalize<<<1, 256>>>(out);
}

// round 6
// speedup vs baseline: 1.3216x; 1.0927x over previous
#include <cuda_runtime.h>
#include <cstdint>

// Problem constants
#define BATCH 4
#define DIN   128
#define HIN   192
#define WIN   192
#define OH    182
#define OW    182
#define OWP   192                            // padded row: 768B = 6 aligned sectors
#define DSTRIDE   (OH * OWP)                 // 34944
#define MIDF      (BATCH * DIN * DSTRIDE)    // 17,891,328 per field
#define N_OUT     15634528.0                 // 4*118*182*182

// k1 tile
#define TY 16
#define TX 32
#define SR 26        // TY + 10 slab rows
#define SRW 44       // 42 cols padded
#define WTW 36       // wt row stride (padded)
#define GX 6         // ceil(182/32)
#define GY 12        // ceil(182/16)

#define NB2 (BATCH * OH)                     // 728 k2 blocks

// Gaussian(sigma=1.5, K=11). constexpr + static indexing => FFMA-imm.
__device__ constexpr float WG[11] = {
    0.00102834f, 0.00759875f, 0.03600077f, 0.10936078f, 0.21300553f,
    0.26601172f,
    0.21300553f, 0.10936078f, 0.03600077f, 0.00759875f, 0.00102834f
};

// Scratch (~358 MB) + per-block partials. Device globals => allowed.
__device__ float g_mid[5ULL * MIDF];
__device__ float g_part[NB2];

// ---------------------------------------------------------------------------
// Kernel 1: per depth slice, fused separable 2D Gaussian over 5 fields.
// W-pass: 208 tasks x 4 x-outputs (register sliding window).
// H-pass: 128 tasks x 4 y-outputs, SCALAR y-streaming (70B smem/output).
// ---------------------------------------------------------------------------
__global__ __launch_bounds__(256, 3)
void k_conv2d(const float* __restrict__ img1, const float* __restrict__ img2) {
    __shared__ float sa[SR][SRW];
    __shared__ float sb[SR][SRW];
    __shared__ float wt[5][SR][WTW];

    const int bz = blockIdx.z;                 // b*DIN + d
    const int y0 = blockIdx.y * TY;
    const int x0 = blockIdx.x * TX;
    const float* p1 = img1 + (size_t)bz * (HIN * WIN);
    const float* p2 = img2 + (size_t)bz * (HIN * WIN);
    const int t = threadIdx.x;

    // ---- slab load: 2 fields x 26 rows x 11 float4 = 572 ----
    for (int i = t; i < 2 * SR * 11; i += 256) {
        int fld = i / (SR * 11);
        int s   = i - fld * (SR * 11);
        int r   = s / 11, c = s - r * 11;
        int gy  = y0 + r;     if (gy > HIN - 1) gy = HIN - 1;
        int gx  = x0 + 4 * c; if (gx > WIN - 4) gx = WIN - 4;
        float4 v = *reinterpret_cast<const float4*>((fld ? p2 : p1) + gy * WIN + gx);
        float (*dst)[SRW] = fld ? sb : sa;
        *reinterpret_cast<float4*>(&dst[r][4 * c]) = v;
    }
    __syncthreads();

    // ---- W pass: 26 rows x 8 quads = 208 tasks, 4 x-outputs each ----
    if (t < SR * 8) {
        const int row = t >> 3;
        const int xs  = (t & 7) * 4;

        float a[16], e[16];
#pragma unroll
        for (int c = 0; c < 4; c++) {
            float4 va = *reinterpret_cast<const float4*>(&sa[row][xs + 4 * c]);
            float4 ve = *reinterpret_cast<const float4*>(&sb[row][xs + 4 * c]);
            a[4*c+0]=va.x; a[4*c+1]=va.y; a[4*c+2]=va.z; a[4*c+3]=va.w;
            e[4*c+0]=ve.x; e[4*c+1]=ve.y; e[4*c+2]=ve.z; e[4*c+3]=ve.w;
        }
        float m1[4]  = {0,0,0,0}, m2[4]  = {0,0,0,0};
        float s11[4] = {0,0,0,0}, s22[4] = {0,0,0,0}, s12[4] = {0,0,0,0};
#pragma unroll
        for (int p = 0; p < 14; p++) {
            float av = a[p], bv = e[p];
            float aa = av * av, bb = bv * bv, ab = av * bv;
#pragma unroll
            for (int j = 0; j < 4; j++) {
                int k = p - j;
                if (k >= 0 && k <= 10) {
                    m1[j]  = fmaf(WG[k], av, m1[j]);
                    m2[j]  = fmaf(WG[k], bv, m2[j]);
                    s11[j] = fmaf(WG[k], aa, s11[j]);
                    s22[j] = fmaf(WG[k], bb, s22[j]);
                    s12[j] = fmaf(WG[k], ab, s12[j]);
                }
            }
        }
        *reinterpret_cast<float4*>(&wt[0][row][xs]) = make_float4(m1[0],  m1[1],  m1[2],  m1[3]);
        *reinterpret_cast<float4*>(&wt[1][row][xs]) = make_float4(m2[0],  m2[1],  m2[2],  m2[3]);
        *reinterpret_cast<float4*>(&wt[2][row][xs]) = make_float4(s11[0], s11[1], s11[2], s11[3]);
        *reinterpret_cast<float4*>(&wt[3][row][xs]) = make_float4(s22[0], s22[1], s22[2], s22[3]);
        *reinterpret_cast<float4*>(&wt[4][row][xs]) = make_float4(s12[0], s12[1], s12[2], s12[3]);
    }
    __syncthreads();

    // ---- H pass: 32 x-cols x 4 y-quads = 128 tasks, y-streaming ----
    if (t < 128) {
        const int x  = t & 31;
        const int ys = (t >> 5) * 4;

        float acc[5][4];
#pragma unroll
        for (int f = 0; f < 5; f++)
#pragma unroll
            for (int j = 0; j < 4; j++) acc[f][j] = 0.f;

#pragma unroll
        for (int p = 0; p < 14; p++) {
#pragma unroll
            for (int f = 0; f < 5; f++) {
                float v = wt[f][ys + p][x];     // lanes = consecutive x -> 1 wavefront
#pragma unroll
                for (int j = 0; j < 4; j++) {
                    int k = p - j;
                    if (k >= 0 && k <= 10)
                        acc[f][j] = fmaf(WG[k], v, acc[f][j]);
                }
            }
        }

        const int ox = x0 + x;
        if (ox < OW) {
            const size_t rowbase = (size_t)bz * DSTRIDE + (size_t)(y0 + ys) * OWP + ox;
#pragma unroll
            for (int j = 0; j < 4; j++) {
                if (y0 + ys + j < OH) {
                    size_t o = rowbase + (size_t)j * OWP;
#pragma unroll
                    for (int f = 0; f < 5; f++)
                        g_mid[(size_t)f * MIDF + o] = acc[f][j];
                }
            }
        }
    }
}

// ---------------------------------------------------------------------------
// Kernel 2: D-conv + SSIM + reduction with a 12-slot ring.
// Iteration d: LOAD slice d (slot d%12), COMPUTE output d-1 (slots r+1..r+11).
// Freshest consumed load is one full iteration old -> latency overlapped.
// ---------------------------------------------------------------------------
__global__ __launch_bounds__(192)
void k_dssim() {
    __shared__ float wsum[6];

    const int by = blockIdx.x;          // b*OH + y
    const int b  = by / OH;
    const int y  = by - b * OH;
    const int w  = threadIdx.x;         // 0..191
    const bool act = (w < OW);
    const int wl = act ? w : 0;

    const size_t base = ((size_t)(b * DIN) * OH + y) * OWP + wl;

    float h[5][12];
    float part = 0.f;

    for (int d0 = 0; d0 < 132; d0 += 12) {
#pragma unroll
        for (int r = 0; r < 12; r++) {
            const int d = d0 + r;                // d % 12 == r
            if (d < DIN) {
                const size_t off = base + (size_t)d * DSTRIDE;
#pragma unroll
                for (int f = 0; f < 5; f++)
                    h[f][r] = g_mid[(size_t)f * MIDF + off];
            }
            if (d >= 11 && d <= DIN) {           // output od = d-1 in [10,127]
                float m1 = 0.f, m2 = 0.f, p11 = 0.f, p22 = 0.f, p12 = 0.f;
#pragma unroll
                for (int k = 0; k < 11; k++) {
                    const int s = (r + 1 + k) % 12;   // slice od-10+k ; static
                    m1  = fmaf(WG[k], h[0][s], m1);
                    m2  = fmaf(WG[k], h[1][s], m2);
                    p11 = fmaf(WG[k], h[2][s], p11);
                    p22 = fmaf(WG[k], h[3][s], p22);
                    p12 = fmaf(WG[k], h[4][s], p12);
                }
                float mu11 = m1 * m1;
                float mu22 = m2 * m2;
                float mu12 = m1 * m2;
                float sg1  = p11 - mu11;
                float sg2  = p22 - mu22;
                float sg12 = p12 - mu12;
                const float C1 = 1e-4f;
                const float C2 = 9e-4f;
                float num = (2.f * mu12 + C1) * (2.f * sg12 + C2);
                float den = (mu11 + mu22 + C1) * (sg1 + sg2 + C2);
                if (act) part += __fdividef(num, den);
            }
        }
    }

    float v = part;
#pragma unroll
    for (int o = 16; o > 0; o >>= 1)
        v += __shfl_down_sync(0xffffffffu, v, o);
    if ((threadIdx.x & 31) == 0) wsum[threadIdx.x >> 5] = v;
    __syncthreads();
    if (threadIdx.x == 0) {
        float s = 0.f;
#pragma unroll
        for (int i = 0; i < 6; i++) s += wsum[i];
        g_part[by] = s;
    }
}

// ---------------------------------------------------------------------------
// Finalize: deterministic double tree over 728 partials.
// ---------------------------------------------------------------------------
__global__ __launch_bounds__(256)
void k_finalize(float* __restrict__ out) {
    __shared__ double sred[256];
    const int t = threadIdx.x;
    double s = 0.0;
    for (int i = t; i < NB2; i += 256) s += (double)g_part[i];
    sred[t] = s;
    __syncthreads();
    for (int o = 128; o > 0; o >>= 1) {
        if (t < o) sred[t] += sred[t + o];
        __syncthreads();
    }
    if (t == 0) out[0] = (float)(sred[0] / N_OUT);
}

extern "C" void kernel_launch(void* const* d_in, const int* in_sizes, int n_in,
                              void* d_out, int out_size) {
    const float* img1 = (const float*)d_in[0];
    const float* img2 = (const float*)d_in[1];
    float* out = (float*)d_out;

    dim3 g1(GX, GY, BATCH * DIN);   // 6 x 12 x 512 = 36,864 blocks
    k_conv2d<<<g1, 256>>>(img1, img2);
    k_dssim<<<NB2, 192>>>();
    k_finalize<<<1, 256>>>(out);
}

// round 8
// speedup vs baseline: 1.5030x; 1.1372x over previous
#include <cuda_runtime.h>
#include <cstdint>

typedef unsigned long long u64;

// Problem constants
#define BATCH 4
#define DIN   128
#define HIN   192
#define WIN   192
#define OH    182
#define OW    182
#define OWP   192
#define DSTRIDE   (OH * OWP)                 // 34944
#define MIDF      (BATCH * DIN * DSTRIDE)    // 17,891,328 per field
#define N_OUT     15634528.0                 // 4*118*182*182

// k1 tile
#define TY 16
#define TX 32
#define SR 26        // TY + 10
#define SRW 44
#define WTW 36
#define GX 6
#define GY 12

#define NB2 (BATCH * OH)                     // 728
#define NBP (NB2 * 2)                        // 1456 partials (D-split x2)

// Gaussian(sigma=1.5, K=11)
__device__ constexpr float WG[11] = {
    0.00102834f, 0.00759875f, 0.03600077f, 0.10936078f, 0.21300553f,
    0.26601172f,
    0.21300553f, 0.10936078f, 0.03600077f, 0.00759875f, 0.00102834f
};

// ---- packed f32x2 helpers (Blackwell FFMA2 via PTX; PTX ISA 8.6+, sm_100+) ----
#define FMA2(d, a, b, c) asm("fma.rn.f32x2 %0, %1, %2, %3;" : "=l"(d) : "l"(a), "l"(b), "l"(c))
#define MUL2(d, a, b)    asm("mul.rn.f32x2 %0, %1, %2;"      : "=l"(d) : "l"(a), "l"(b))
#define PACK2(d, lo, hi) asm("mov.b64 %0, {%1, %2};"         : "=l"(d) : "f"(lo), "f"(hi))
#define UNPACK2(lo, hi, v) asm("mov.b64 {%0, %1}, %2;"       : "=f"(lo), "=f"(hi) : "l"(v))

// Scratch: A=(mu1,mu2) f32x2, B=(s11,s22) f32x2, C=s12 f32.  ~358 MB total.
__device__ u64   g_midA[MIDF];
__device__ u64   g_midB[MIDF];
__device__ float g_midC[MIDF];
__device__ float g_part[NBP];

// ---------------------------------------------------------------------------
// Kernel 1: per depth slice, separable 2D Gaussian over packed fields.
// W-pass: 208 tasks x 4 x-outputs (register sliding window, packed FMA).
// H-pass: 128 tasks x 4 y-outputs, y-streaming, packed FMA.
// ---------------------------------------------------------------------------
__global__ __launch_bounds__(256, 3)
void k_conv2d(const float* __restrict__ img1, const float* __restrict__ img2) {
    __shared__ float sa[SR][SRW];
    __shared__ float sb[SR][SRW];
    __shared__ u64   wtA[SR][WTW];
    __shared__ u64   wtB[SR][WTW];
    __shared__ float wtC[SR][WTW];

    const int bz = blockIdx.z;
    const int y0 = blockIdx.y * TY;
    const int x0 = blockIdx.x * TX;
    const float* p1 = img1 + (size_t)bz * (HIN * WIN);
    const float* p2 = img2 + (size_t)bz * (HIN * WIN);
    const int t = threadIdx.x;

    u64 wp[11];
#pragma unroll
    for (int k = 0; k < 11; k++) PACK2(wp[k], WG[k], WG[k]);

    // ---- slab load: 2 fields x 26 rows x 11 float4 ----
    for (int i = t; i < 2 * SR * 11; i += 256) {
        int fld = i / (SR * 11);
        int s   = i - fld * (SR * 11);
        int r   = s / 11, c = s - r * 11;
        int gy  = y0 + r;     if (gy > HIN - 1) gy = HIN - 1;
        int gx  = x0 + 4 * c; if (gx > WIN - 4) gx = WIN - 4;
        float4 v = *reinterpret_cast<const float4*>((fld ? p2 : p1) + gy * WIN + gx);
        float (*dst)[SRW] = fld ? sb : sa;
        *reinterpret_cast<float4*>(&dst[r][4 * c]) = v;
    }
    __syncthreads();

    // ---- W pass: 26 rows x 8 quads = 208 tasks ----
    if (t < SR * 8) {
        const int row = t >> 3;
        const int xs  = (t & 7) * 4;

        float a[16], e[16];
#pragma unroll
        for (int c = 0; c < 4; c++) {
            float4 va = *reinterpret_cast<const float4*>(&sa[row][xs + 4 * c]);
            float4 ve = *reinterpret_cast<const float4*>(&sb[row][xs + 4 * c]);
            a[4*c+0]=va.x; a[4*c+1]=va.y; a[4*c+2]=va.z; a[4*c+3]=va.w;
            e[4*c+0]=ve.x; e[4*c+1]=ve.y; e[4*c+2]=ve.z; e[4*c+3]=ve.w;
        }

        u64 m12[4], s1122[4];
        float s12[4];
#pragma unroll
        for (int j = 0; j < 4; j++) { m12[j] = 0ULL; s1122[j] = 0ULL; s12[j] = 0.f; }

#pragma unroll
        for (int p = 0; p < 14; p++) {
            u64 pv, sq;
            PACK2(pv, a[p], e[p]);
            MUL2(sq, pv, pv);
            float ab = a[p] * e[p];
#pragma unroll
            for (int j = 0; j < 4; j++) {
                int k = p - j;
                if (k >= 0 && k <= 10) {
                    FMA2(m12[j],   wp[k], pv, m12[j]);
                    FMA2(s1122[j], wp[k], sq, s1122[j]);
                    s12[j] = fmaf(WG[k], ab, s12[j]);
                }
            }
        }
        *reinterpret_cast<ulonglong2*>(&wtA[row][xs])     = make_ulonglong2(m12[0], m12[1]);
        *reinterpret_cast<ulonglong2*>(&wtA[row][xs + 2]) = make_ulonglong2(m12[2], m12[3]);
        *reinterpret_cast<ulonglong2*>(&wtB[row][xs])     = make_ulonglong2(s1122[0], s1122[1]);
        *reinterpret_cast<ulonglong2*>(&wtB[row][xs + 2]) = make_ulonglong2(s1122[2], s1122[3]);
        *reinterpret_cast<float4*>(&wtC[row][xs]) = make_float4(s12[0], s12[1], s12[2], s12[3]);
    }
    __syncthreads();

    // ---- H pass: 32 x-cols x 4 y-quads = 128 tasks, y-streaming ----
    if (t < 128) {
        const int x  = t & 31;
        const int ys = (t >> 5) * 4;

        u64 accA[4], accB[4];
        float accC[4];
#pragma unroll
        for (int j = 0; j < 4; j++) { accA[j] = 0ULL; accB[j] = 0ULL; accC[j] = 0.f; }

#pragma unroll
        for (int p = 0; p < 14; p++) {
            u64 vA = wtA[ys + p][x];
            u64 vB = wtB[ys + p][x];
            float vC = wtC[ys + p][x];
#pragma unroll
            for (int j = 0; j < 4; j++) {
                int k = p - j;
                if (k >= 0 && k <= 10) {
                    FMA2(accA[j], wp[k], vA, accA[j]);
                    FMA2(accB[j], wp[k], vB, accB[j]);
                    accC[j] = fmaf(WG[k], vC, accC[j]);
                }
            }
        }

        const int ox = x0 + x;
        if (ox < OW) {
            const size_t rowbase = (size_t)bz * DSTRIDE + (size_t)(y0 + ys) * OWP + ox;
#pragma unroll
            for (int j = 0; j < 4; j++) {
                if (y0 + ys + j < OH) {
                    size_t o = rowbase + (size_t)j * OWP;
                    g_midA[o] = accA[j];
                    g_midB[o] = accB[j];
                    g_midC[o] = accC[j];
                }
            }
        }
    }
}

// ---------------------------------------------------------------------------
// Kernel 2: D-conv + SSIM + reduction. D-split x2 (1456 blocks).
// 12-slot register ring, one-iteration load/compute offset, packed FMAs.
// Chunk c: outputs od in [10+59c, 68+59c], slices d0=59c .. d0+68.
// ---------------------------------------------------------------------------
__global__ __launch_bounds__(192)
void k_dssim() {
    __shared__ float wsum[6];

    const int by = blockIdx.x;          // b*OH + y
    const int c  = blockIdx.y;          // D-chunk
    const int b  = by / OH;
    const int y  = by - b * OH;
    const int w  = threadIdx.x;         // 0..191
    const bool act = (w < OW);
    const int wl = act ? w : 0;
    const int d0 = c * 59;

    const size_t base = ((size_t)(b * DIN) * OH + y) * OWP + wl;

    u64 wp[11];
#pragma unroll
    for (int k = 0; k < 11; k++) PACK2(wp[k], WG[k], WG[k]);

    u64 hA[12], hB[12];
    float hC[12];
    float part = 0.f;

    for (int i0 = 0; i0 < 72; i0 += 12) {
#pragma unroll
        for (int r = 0; r < 12; r++) {
            const int i = i0 + r;                // ring slot == i % 12 == r
            if (i < 69) {                        // load slice d0+i
                const size_t off = base + (size_t)(d0 + i) * DSTRIDE;
                hA[r] = g_midA[off];
                hB[r] = g_midB[off];
                hC[r] = g_midC[off];
            }
            if (i >= 11 && i <= 69) {            // compute output d0+i-1
                u64 M12 = 0ULL, S1122 = 0ULL;
                float p12 = 0.f;
#pragma unroll
                for (int k = 0; k < 11; k++) {
                    const int s = (r + 1 + k) % 12;   // static after unroll
                    FMA2(M12,   wp[k], hA[s], M12);
                    FMA2(S1122, wp[k], hB[s], S1122);
                    p12 = fmaf(WG[k], hC[s], p12);
                }
                float m1, m2, p11, p22;
                UNPACK2(m1, m2, M12);
                UNPACK2(p11, p22, S1122);
                float mu11 = m1 * m1;
                float mu22 = m2 * m2;
                float mu12 = m1 * m2;
                float sg1  = p11 - mu11;
                float sg2  = p22 - mu22;
                float sg12 = p12 - mu12;
                const float C1 = 1e-4f;
                const float C2 = 9e-4f;
                float num = (2.f * mu12 + C1) * (2.f * sg12 + C2);
                float den = (mu11 + mu22 + C1) * (sg1 + sg2 + C2);
                if (act) part += __fdividef(num, den);
            }
        }
    }

    float v = part;
#pragma unroll
    for (int o = 16; o > 0; o >>= 1)
        v += __shfl_down_sync(0xffffffffu, v, o);
    if ((threadIdx.x & 31) == 0) wsum[threadIdx.x >> 5] = v;
    __syncthreads();
    if (threadIdx.x == 0) {
        float s = 0.f;
#pragma unroll
        for (int i = 0; i < 6; i++) s += wsum[i];
        g_part[c * NB2 + by] = s;
    }
}

// ---------------------------------------------------------------------------
// Finalize: deterministic double tree over 1456 partials.
// ---------------------------------------------------------------------------
__global__ __launch_bounds__(256)
void k_finalize(float* __restrict__ out) {
    __shared__ double sred[256];
    const int t = threadIdx.x;
    double s = 0.0;
    for (int i = t; i < NBP; i += 256) s += (double)g_part[i];
    sred[t] = s;
    __syncthreads();
    for (int o = 128; o > 0; o >>= 1) {
        if (t < o) sred[t] += sred[t + o];
        __syncthreads();
    }
    if (t == 0) out[0] = (float)(sred[0] / N_OUT);
}

extern "C" void kernel_launch(void* const* d_in, const int* in_sizes, int n_in,
                              void* d_out, int out_size) {
    const float* img1 = (const float*)d_in[0];
    const float* img2 = (const float*)d_in[1];
    float* out = (float*)d_out;

    dim3 g1(GX, GY, BATCH * DIN);   // 36,864 blocks
    k_conv2d<<<g1, 256>>>(img1, img2);
    k_dssim<<<dim3(NB2, 2), 192>>>();
    k_finalize<<<1, 256>>>(out);
}

// round 9
// speedup vs baseline: 1.5208x; 1.0119x over previous
#include <cuda_runtime.h>
#include <cstdint>

typedef unsigned long long u64;

// Problem constants
#define BATCH 4
#define DIN   128
#define HIN   192
#define WIN   192
#define OH    182
#define OW    182
#define OWP   192
#define DSTRIDE   (OH * OWP)                 // 34944
#define MIDF      (BATCH * DIN * DSTRIDE)    // 17,891,328 per field
#define N_OUT     15634528.0                 // 4*118*182*182

// k1 tile: 32x32 outputs
#define TY 32
#define TX 32
#define SR 42        // TY + 10 slab rows
#define SRW 44       // 42 cols padded
#define WTW 36       // wt row stride
#define GX 6         // ceil(182/32)
#define GY 6

#define NB2 (BATCH * OH)                     // 728
#define NBP (NB2 * 2)                        // 1456 partials (D-split x2)

// Gaussian(sigma=1.5, K=11)
__device__ constexpr float WG[11] = {
    0.00102834f, 0.00759875f, 0.03600077f, 0.10936078f, 0.21300553f,
    0.26601172f,
    0.21300553f, 0.10936078f, 0.03600077f, 0.00759875f, 0.00102834f
};

// ---- packed f32x2 helpers (Blackwell FFMA2 via PTX) ----
#define FMA2(d, a, b, c) asm("fma.rn.f32x2 %0, %1, %2, %3;" : "=l"(d) : "l"(a), "l"(b), "l"(c))
#define MUL2(d, a, b)    asm("mul.rn.f32x2 %0, %1, %2;"      : "=l"(d) : "l"(a), "l"(b))
#define PACK2(d, lo, hi) asm("mov.b64 %0, {%1, %2};"         : "=l"(d) : "f"(lo), "f"(hi))
#define UNPACK2(lo, hi, v) asm("mov.b64 {%0, %1}, %2;"       : "=f"(lo), "=f"(hi) : "l"(v))

// Scratch: A=(mu1,mu2) f32x2, B=(s11,s22) f32x2, C=s12 f32.  ~358 MB total.
__device__ u64   g_midA[MIDF];
__device__ u64   g_midB[MIDF];
__device__ float g_midC[MIDF];
__device__ float g_part[NBP];

// ---------------------------------------------------------------------------
// Kernel 1: per depth slice, separable 2D Gaussian over packed fields.
// Tile 32x32. W-pass: 336 tasks x 4 x-outputs. H-pass: 128 tasks x 8 y-outputs.
// ---------------------------------------------------------------------------
__global__ __launch_bounds__(256, 3)
void k_conv2d(const float* __restrict__ img1, const float* __restrict__ img2) {
    __shared__ float sa[SR][SRW];
    __shared__ float sb[SR][SRW];
    __shared__ u64   wtA[SR][WTW];
    __shared__ u64   wtB[SR][WTW];
    __shared__ float wtC[SR][WTW];

    const int bz = blockIdx.z;
    const int y0 = blockIdx.y * TY;
    const int x0 = blockIdx.x * TX;
    const float* p1 = img1 + (size_t)bz * (HIN * WIN);
    const float* p2 = img2 + (size_t)bz * (HIN * WIN);
    const int t = threadIdx.x;

    u64 wp[11];
#pragma unroll
    for (int k = 0; k < 11; k++) PACK2(wp[k], WG[k], WG[k]);

    // ---- slab load: 2 fields x 42 rows x 11 float4 = 924 tasks ----
#pragma unroll 1
    for (int i = t; i < 2 * SR * 11; i += 256) {
        int fld = i / (SR * 11);
        int s   = i - fld * (SR * 11);
        int r   = s / 11, c = s - r * 11;
        int gy  = y0 + r;     if (gy > HIN - 1) gy = HIN - 1;
        int gx  = x0 + 4 * c; if (gx > WIN - 4) gx = WIN - 4;
        float4 v = *reinterpret_cast<const float4*>((fld ? p2 : p1) + gy * WIN + gx);
        float (*dst)[SRW] = fld ? sb : sa;
        *reinterpret_cast<float4*>(&dst[r][4 * c]) = v;
    }
    __syncthreads();

    // ---- W pass: 42 rows x 8 quads = 336 tasks, 4 x-outputs each ----
#pragma unroll 1
    for (int tt = t; tt < SR * 8; tt += 256) {
        const int row = tt >> 3;
        const int xs  = (tt & 7) * 4;

        float a[16], e[16];
#pragma unroll
        for (int c = 0; c < 4; c++) {
            float4 va = *reinterpret_cast<const float4*>(&sa[row][xs + 4 * c]);
            float4 ve = *reinterpret_cast<const float4*>(&sb[row][xs + 4 * c]);
            a[4*c+0]=va.x; a[4*c+1]=va.y; a[4*c+2]=va.z; a[4*c+3]=va.w;
            e[4*c+0]=ve.x; e[4*c+1]=ve.y; e[4*c+2]=ve.z; e[4*c+3]=ve.w;
        }

        u64 m12[4], s1122[4];
        float s12[4];
#pragma unroll
        for (int j = 0; j < 4; j++) { m12[j] = 0ULL; s1122[j] = 0ULL; s12[j] = 0.f; }

#pragma unroll
        for (int p = 0; p < 14; p++) {
            u64 pv, sq;
            PACK2(pv, a[p], e[p]);
            MUL2(sq, pv, pv);
            float ab = a[p] * e[p];
#pragma unroll
            for (int j = 0; j < 4; j++) {
                int k = p - j;
                if (k >= 0 && k <= 10) {
                    FMA2(m12[j],   wp[k], pv, m12[j]);
                    FMA2(s1122[j], wp[k], sq, s1122[j]);
                    s12[j] = fmaf(WG[k], ab, s12[j]);
                }
            }
        }
        *reinterpret_cast<ulonglong2*>(&wtA[row][xs])     = make_ulonglong2(m12[0], m12[1]);
        *reinterpret_cast<ulonglong2*>(&wtA[row][xs + 2]) = make_ulonglong2(m12[2], m12[3]);
        *reinterpret_cast<ulonglong2*>(&wtB[row][xs])     = make_ulonglong2(s1122[0], s1122[1]);
        *reinterpret_cast<ulonglong2*>(&wtB[row][xs + 2]) = make_ulonglong2(s1122[2], s1122[3]);
        *reinterpret_cast<float4*>(&wtC[row][xs]) = make_float4(s12[0], s12[1], s12[2], s12[3]);
    }
    __syncthreads();

    // ---- H pass: 32 x-cols x 4 y-octs = 128 tasks, 8 y-outputs each ----
    if (t < 128) {
        const int x  = t & 31;
        const int ys = (t >> 5) * 8;

        u64 accA[8], accB[8];
        float accC[8];
#pragma unroll
        for (int j = 0; j < 8; j++) { accA[j] = 0ULL; accB[j] = 0ULL; accC[j] = 0.f; }

#pragma unroll
        for (int p = 0; p < 18; p++) {
            u64 vA = wtA[ys + p][x];
            u64 vB = wtB[ys + p][x];
            float vC = wtC[ys + p][x];
#pragma unroll
            for (int j = 0; j < 8; j++) {
                int k = p - j;
                if (k >= 0 && k <= 10) {
                    FMA2(accA[j], wp[k], vA, accA[j]);
                    FMA2(accB[j], wp[k], vB, accB[j]);
                    accC[j] = fmaf(WG[k], vC, accC[j]);
                }
            }
        }

        const int ox = x0 + x;
        if (ox < OW) {
            const size_t rowbase = (size_t)bz * DSTRIDE + (size_t)(y0 + ys) * OWP + ox;
#pragma unroll
            for (int j = 0; j < 8; j++) {
                if (y0 + ys + j < OH) {
                    size_t o = rowbase + (size_t)j * OWP;
                    g_midA[o] = accA[j];
                    g_midB[o] = accB[j];
                    g_midC[o] = accC[j];
                }
            }
        }
    }
}

// ---------------------------------------------------------------------------
// Kernel 2: D-conv + SSIM + reduction. D-split x2 (1456 blocks).
// 12-slot register ring, one-iteration load/compute offset, packed FMAs.
// ---------------------------------------------------------------------------
__global__ __launch_bounds__(192)
void k_dssim() {
    __shared__ float wsum[6];

    const int by = blockIdx.x;          // b*OH + y
    const int c  = blockIdx.y;          // D-chunk
    const int b  = by / OH;
    const int y  = by - b * OH;
    const int w  = threadIdx.x;         // 0..191
    const bool act = (w < OW);
    const int wl = act ? w : 0;
    const int d0 = c * 59;

    const size_t base = ((size_t)(b * DIN) * OH + y) * OWP + wl;

    u64 wp[11];
#pragma unroll
    for (int k = 0; k < 11; k++) PACK2(wp[k], WG[k], WG[k]);

    u64 hA[12], hB[12];
    float hC[12];
    float part = 0.f;

    for (int i0 = 0; i0 < 72; i0 += 12) {
#pragma unroll
        for (int r = 0; r < 12; r++) {
            const int i = i0 + r;                // ring slot == i % 12 == r
            if (i < 69) {                        // load slice d0+i
                const size_t off = base + (size_t)(d0 + i) * DSTRIDE;
                hA[r] = g_midA[off];
                hB[r] = g_midB[off];
                hC[r] = g_midC[off];
            }
            if (i >= 11 && i <= 69) {            // compute output d0+i-1
                u64 M12 = 0ULL, S1122 = 0ULL;
                float p12 = 0.f;
#pragma unroll
                for (int k = 0; k < 11; k++) {
                    const int s = (r + 1 + k) % 12;   // static after unroll
                    FMA2(M12,   wp[k], hA[s], M12);
                    FMA2(S1122, wp[k], hB[s], S1122);
                    p12 = fmaf(WG[k], hC[s], p12);
                }
                float m1, m2, p11, p22;
                UNPACK2(m1, m2, M12);
                UNPACK2(p11, p22, S1122);
                float mu11 = m1 * m1;
                float mu22 = m2 * m2;
                float mu12 = m1 * m2;
                float sg1  = p11 - mu11;
                float sg2  = p22 - mu22;
                float sg12 = p12 - mu12;
                const float C1 = 1e-4f;
                const float C2 = 9e-4f;
                float num = (2.f * mu12 + C1) * (2.f * sg12 + C2);
                float den = (mu11 + mu22 + C1) * (sg1 + sg2 + C2);
                if (act) part += __fdividef(num, den);
            }
        }
    }

    float v = part;
#pragma unroll
    for (int o = 16; o > 0; o >>= 1)
        v += __shfl_down_sync(0xffffffffu, v, o);
    if ((threadIdx.x & 31) == 0) wsum[threadIdx.x >> 5] = v;
    __syncthreads();
    if (threadIdx.x == 0) {
        float s = 0.f;
#pragma unroll
        for (int i = 0; i < 6; i++) s += wsum[i];
        g_part[c * NB2 + by] = s;
    }
}

// ---------------------------------------------------------------------------
// Finalize: deterministic double tree over 1456 partials.
// ---------------------------------------------------------------------------
__global__ __launch_bounds__(256)
void k_finalize(float* __restrict__ out) {
    __shared__ double sred[256];
    const int t = threadIdx.x;
    double s = 0.0;
    for (int i = t; i < NBP; i += 256) s += (double)g_part[i];
    sred[t] = s;
    __syncthreads();
    for (int o = 128; o > 0; o >>= 1) {
        if (t < o) sred[t] += sred[t + o];
        __syncthreads();
    }
    if (t == 0) out[0] = (float)(sred[0] / N_OUT);
}

extern "C" void kernel_launch(void* const* d_in, const int* in_sizes, int n_in,
                              void* d_out, int out_size) {
    const float* img1 = (const float*)d_in[0];
    const float* img2 = (const float*)d_in[1];
    float* out = (float*)d_out;

    dim3 g1(GX, GY, BATCH * DIN);   // 6 x 6 x 512 = 18,432 blocks
    k_conv2d<<<g1, 256>>>(img1, img2);
    k_dssim<<<dim3(NB2, 2), 192>>>();
    k_finalize<<<1, 256>>>(out);
}

// round 10
// speedup vs baseline: 1.7126x; 1.1261x over previous
#include <cuda_runtime.h>
#include <cstdint>

typedef unsigned long long u64;

// Problem constants
#define BATCH 4
#define DIN   128
#define HIN   192
#define WIN   192
#define OH    182
#define OW    182
#define OWP   192
#define DSTRIDE   (OH * OWP)                 // 34944
#define MIDF      (BATCH * DIN * DSTRIDE)    // 17,891,328 per field
#define N_OUT     15634528.0                 // 4*118*182*182

// k1 tile: 32x32 outputs
#define TY 32
#define TX 32
#define SR 42        // TY + 10 slab rows
#define SRW 44       // 42 cols padded
#define WTW 36       // wt row stride
#define GX 6         // ceil(182/32)
#define GY 6

#define NB2 (BATCH * OH)                     // 728
#define NBP (NB2 * 2)                        // 1456 partials (D-split x2)

// Gaussian(sigma=1.5, K=11)
__device__ constexpr float WG[11] = {
    0.00102834f, 0.00759875f, 0.03600077f, 0.10936078f, 0.21300553f,
    0.26601172f,
    0.21300553f, 0.10936078f, 0.03600077f, 0.00759875f, 0.00102834f
};

// ---- packed f32x2 helpers (Blackwell FFMA2 via PTX) ----
#define FMA2(d, a, b, c) asm("fma.rn.f32x2 %0, %1, %2, %3;" : "=l"(d) : "l"(a), "l"(b), "l"(c))
#define MUL2(d, a, b)    asm("mul.rn.f32x2 %0, %1, %2;"      : "=l"(d) : "l"(a), "l"(b))
#define PACK2(d, lo, hi) asm("mov.b64 %0, {%1, %2};"         : "=l"(d) : "f"(lo), "f"(hi))
#define UNPACK2(lo, hi, v) asm("mov.b64 {%0, %1}, %2;"       : "=f"(lo), "=f"(hi) : "l"(v))

// Scratch: A=(mu1,mu2) f32x2, B=(s11,s22) f32x2, C=s12 f32.  ~358 MB total.
__device__ u64   g_midA[MIDF];
__device__ u64   g_midB[MIDF];
__device__ float g_midC[MIDF];
__device__ float g_part[NBP];

// ---------------------------------------------------------------------------
// Kernel 1: per depth slice, separable 2D Gaussian over packed fields.
// Tile 32x32. W-pass: 336 tasks x 4 x-outputs. H-pass: 128 tasks x 8 y-outputs.
// launch_bounds(256,4): cap 64 regs -> 4 blocks/SM (occupancy experiment).
// ---------------------------------------------------------------------------
__global__ __launch_bounds__(256, 4)
void k_conv2d(const float* __restrict__ img1, const float* __restrict__ img2) {
    __shared__ float sa[SR][SRW];
    __shared__ float sb[SR][SRW];
    __shared__ u64   wtA[SR][WTW];
    __shared__ u64   wtB[SR][WTW];
    __shared__ float wtC[SR][WTW];

    const int bz = blockIdx.z;
    const int y0 = blockIdx.y * TY;
    const int x0 = blockIdx.x * TX;
    const float* p1 = img1 + (size_t)bz * (HIN * WIN);
    const float* p2 = img2 + (size_t)bz * (HIN * WIN);
    const int t = threadIdx.x;

    u64 wp[11];
#pragma unroll
    for (int k = 0; k < 11; k++) PACK2(wp[k], WG[k], WG[k]);

    // ---- slab load: 2 fields x 42 rows x 11 float4 = 924 tasks ----
#pragma unroll 1
    for (int i = t; i < 2 * SR * 11; i += 256) {
        int fld = i / (SR * 11);
        int s   = i - fld * (SR * 11);
        int r   = s / 11, c = s - r * 11;
        int gy  = y0 + r;     if (gy > HIN - 1) gy = HIN - 1;
        int gx  = x0 + 4 * c; if (gx > WIN - 4) gx = WIN - 4;
        float4 v = *reinterpret_cast<const float4*>((fld ? p2 : p1) + gy * WIN + gx);
        float (*dst)[SRW] = fld ? sb : sa;
        *reinterpret_cast<float4*>(&dst[r][4 * c]) = v;
    }
    __syncthreads();

    // ---- W pass: 42 rows x 8 quads = 336 tasks, 4 x-outputs each ----
#pragma unroll 1
    for (int tt = t; tt < SR * 8; tt += 256) {
        const int row = tt >> 3;
        const int xs  = (tt & 7) * 4;

        float a[16], e[16];
#pragma unroll
        for (int c = 0; c < 4; c++) {
            float4 va = *reinterpret_cast<const float4*>(&sa[row][xs + 4 * c]);
            float4 ve = *reinterpret_cast<const float4*>(&sb[row][xs + 4 * c]);
            a[4*c+0]=va.x; a[4*c+1]=va.y; a[4*c+2]=va.z; a[4*c+3]=va.w;
            e[4*c+0]=ve.x; e[4*c+1]=ve.y; e[4*c+2]=ve.z; e[4*c+3]=ve.w;
        }

        u64 m12[4], s1122[4];
        float s12[4];
#pragma unroll
        for (int j = 0; j < 4; j++) { m12[j] = 0ULL; s1122[j] = 0ULL; s12[j] = 0.f; }

#pragma unroll
        for (int p = 0; p < 14; p++) {
            u64 pv, sq;
            PACK2(pv, a[p], e[p]);
            MUL2(sq, pv, pv);
            float ab = a[p] * e[p];
#pragma unroll
            for (int j = 0; j < 4; j++) {
                int k = p - j;
                if (k >= 0 && k <= 10) {
                    FMA2(m12[j],   wp[k], pv, m12[j]);
                    FMA2(s1122[j], wp[k], sq, s1122[j]);
                    s12[j] = fmaf(WG[k], ab, s12[j]);
                }
            }
        }
        *reinterpret_cast<ulonglong2*>(&wtA[row][xs])     = make_ulonglong2(m12[0], m12[1]);
        *reinterpret_cast<ulonglong2*>(&wtA[row][xs + 2]) = make_ulonglong2(m12[2], m12[3]);
        *reinterpret_cast<ulonglong2*>(&wtB[row][xs])     = make_ulonglong2(s1122[0], s1122[1]);
        *reinterpret_cast<ulonglong2*>(&wtB[row][xs + 2]) = make_ulonglong2(s1122[2], s1122[3]);
        *reinterpret_cast<float4*>(&wtC[row][xs]) = make_float4(s12[0], s12[1], s12[2], s12[3]);
    }
    __syncthreads();

    // ---- H pass: 32 x-cols x 4 y-octs = 128 tasks, 8 y-outputs each ----
    if (t < 128) {
        const int x  = t & 31;
        const int ys = (t >> 5) * 8;

        u64 accA[8], accB[8];
        float accC[8];
#pragma unroll
        for (int j = 0; j < 8; j++) { accA[j] = 0ULL; accB[j] = 0ULL; accC[j] = 0.f; }

#pragma unroll
        for (int p = 0; p < 18; p++) {
            u64 vA = wtA[ys + p][x];
            u64 vB = wtB[ys + p][x];
            float vC = wtC[ys + p][x];
#pragma unroll
            for (int j = 0; j < 8; j++) {
                int k = p - j;
                if (k >= 0 && k <= 10) {
                    FMA2(accA[j], wp[k], vA, accA[j]);
                    FMA2(accB[j], wp[k], vB, accB[j]);
                    accC[j] = fmaf(WG[k], vC, accC[j]);
                }
            }
        }

        const int ox = x0 + x;
        if (ox < OW) {
            const size_t rowbase = (size_t)bz * DSTRIDE + (size_t)(y0 + ys) * OWP + ox;
#pragma unroll
            for (int j = 0; j < 8; j++) {
                if (y0 + ys + j < OH) {
                    size_t o = rowbase + (size_t)j * OWP;
                    g_midA[o] = accA[j];
                    g_midB[o] = accB[j];
                    g_midC[o] = accC[j];
                }
            }
        }
    }
}

// ---------------------------------------------------------------------------
// Kernel 2: D-conv + SSIM + reduction. D-split x2 (1456 blocks).
// 12-slot register ring, one-iteration load/compute offset, packed FMAs.
// (Frozen this round for attribution.)
// ---------------------------------------------------------------------------
__global__ __launch_bounds__(192)
void k_dssim() {
    __shared__ float wsum[6];

    const int by = blockIdx.x;          // b*OH + y
    const int c  = blockIdx.y;          // D-chunk
    const int b  = by / OH;
    const int y  = by - b * OH;
    const int w  = threadIdx.x;         // 0..191
    const bool act = (w < OW);
    const int wl = act ? w : 0;
    const int d0 = c * 59;

    const size_t base = ((size_t)(b * DIN) * OH + y) * OWP + wl;

    u64 wp[11];
#pragma unroll
    for (int k = 0; k < 11; k++) PACK2(wp[k], WG[k], WG[k]);

    u64 hA[12], hB[12];
    float hC[12];
    float part = 0.f;

    for (int i0 = 0; i0 < 72; i0 += 12) {
#pragma unroll
        for (int r = 0; r < 12; r++) {
            const int i = i0 + r;                // ring slot == i % 12 == r
            if (i < 69) {                        // load slice d0+i
                const size_t off = base + (size_t)(d0 + i) * DSTRIDE;
                hA[r] = g_midA[off];
                hB[r] = g_midB[off];
                hC[r] = g_midC[off];
            }
            if (i >= 11 && i <= 69) {            // compute output d0+i-1
                u64 M12 = 0ULL, S1122 = 0ULL;
                float p12 = 0.f;
#pragma unroll
                for (int k = 0; k < 11; k++) {
                    const int s = (r + 1 + k) % 12;   // static after unroll
                    FMA2(M12,   wp[k], hA[s], M12);
                    FMA2(S1122, wp[k], hB[s], S1122);
                    p12 = fmaf(WG[k], hC[s], p12);
                }
                float m1, m2, p11, p22;
                UNPACK2(m1, m2, M12);
                UNPACK2(p11, p22, S1122);
                float mu11 = m1 * m1;
                float mu22 = m2 * m2;
                float mu12 = m1 * m2;
                float sg1  = p11 - mu11;
                float sg2  = p22 - mu22;
                float sg12 = p12 - mu12;
                const float C1 = 1e-4f;
                const float C2 = 9e-4f;
                float num = (2.f * mu12 + C1) * (2.f * sg12 + C2);
                float den = (mu11 + mu22 + C1) * (sg1 + sg2 + C2);
                if (act) part += __fdividef(num, den);
            }
        }
    }

    float v = part;
#pragma unroll
    for (int o = 16; o > 0; o >>= 1)
        v += __shfl_down_sync(0xffffffffu, v, o);
    if ((threadIdx.x & 31) == 0) wsum[threadIdx.x >> 5] = v;
    __syncthreads();
    if (threadIdx.x == 0) {
        float s = 0.f;
#pragma unroll
        for (int i = 0; i < 6; i++) s += wsum[i];
        g_part[c * NB2 + by] = s;
    }
}

// ---------------------------------------------------------------------------
// Finalize: deterministic double tree over 1456 partials.
// ---------------------------------------------------------------------------
__global__ __launch_bounds__(256)
void k_finalize(float* __restrict__ out) {
    __shared__ double sred[256];
    const int t = threadIdx.x;
    double s = 0.0;
    for (int i = t; i < NBP; i += 256) s += (double)g_part[i];
    sred[t] = s;
    __syncthreads();
    for (int o = 128; o > 0; o >>= 1) {
        if (t < o) sred[t] += sred[t + o];
        __syncthreads();
    }
    if (t == 0) out[0] = (float)(sred[0] / N_OUT);
}

extern "C" void kernel_launch(void* const* d_in, const int* in_sizes, int n_in,
                              void* d_out, int out_size) {
    const float* img1 = (const float*)d_in[0];
    const float* img2 = (const float*)d_in[1];
    float* out = (float*)d_out;

    dim3 g1(GX, GY, BATCH * DIN);   // 6 x 6 x 512 = 18,432 blocks
    k_conv2d<<<g1, 256>>>(img1, img2);
    k_dssim<<<dim3(NB2, 2), 192>>>();
    k_finalize<<<1, 256>>>(out);
}

// round 11
// speedup vs baseline: 1.7277x; 1.0088x over previous
#include <cuda_runtime.h>
#include <cstdint>

typedef unsigned long long u64;

// Problem constants
#define BATCH 4
#define DIN   128
#define HIN   192
#define WIN   192
#define OH    182
#define OW    182
#define OWP   192
#define DSTRIDE   (OH * OWP)                 // 34944
#define MIDF      (BATCH * DIN * DSTRIDE)    // 17,891,328 per field
#define N_OUT     15634528.0                 // 4*118*182*182

// k1 tile: 32x32 outputs
#define TY 32
#define TX 32
#define SR 42        // TY + 10 slab rows
#define SRW 44       // 42 cols padded
#define WTW 36       // wt row stride
#define GX 6         // ceil(182/32)
#define GY 6

#define NB2 (BATCH * OH)                     // 728
#define NBP (NB2 * 2)                        // 1456 partials (D-split x2)

// Gaussian(sigma=1.5, K=11)
__device__ constexpr float WG[11] = {
    0.00102834f, 0.00759875f, 0.03600077f, 0.10936078f, 0.21300553f,
    0.26601172f,
    0.21300553f, 0.10936078f, 0.03600077f, 0.00759875f, 0.00102834f
};

// ---- packed f32x2 helpers (Blackwell FFMA2 via PTX) ----
#define FMA2(d, a, b, c) asm("fma.rn.f32x2 %0, %1, %2, %3;" : "=l"(d) : "l"(a), "l"(b), "l"(c))
#define MUL2(d, a, b)    asm("mul.rn.f32x2 %0, %1, %2;"      : "=l"(d) : "l"(a), "l"(b))
#define PACK2(d, lo, hi) asm("mov.b64 %0, {%1, %2};"         : "=l"(d) : "f"(lo), "f"(hi))
#define UNPACK2(lo, hi, v) asm("mov.b64 {%0, %1}, %2;"       : "=f"(lo), "=f"(hi) : "l"(v))

// Scratch: A=(mu1,mu2) f32x2, B=(s11,s22) f32x2, C=s12 f32.  ~358 MB total.
__device__ u64   g_midA[MIDF];
__device__ u64   g_midB[MIDF];
__device__ float g_midC[MIDF];
__device__ float g_part[NBP];

// ---------------------------------------------------------------------------
// Kernel 1: per depth slice, separable 2D Gaussian over packed fields.
// Tile 32x32. W-pass: 336 tasks x 4 x-outputs.
// H-pass: 256 tasks x 4 y-outputs (FULL thread utilization this round).
// ---------------------------------------------------------------------------
__global__ __launch_bounds__(256, 4)
void k_conv2d(const float* __restrict__ img1, const float* __restrict__ img2) {
    __shared__ float sa[SR][SRW];
    __shared__ float sb[SR][SRW];
    __shared__ u64   wtA[SR][WTW];
    __shared__ u64   wtB[SR][WTW];
    __shared__ float wtC[SR][WTW];

    const int bz = blockIdx.z;
    const int y0 = blockIdx.y * TY;
    const int x0 = blockIdx.x * TX;
    const float* p1 = img1 + (size_t)bz * (HIN * WIN);
    const float* p2 = img2 + (size_t)bz * (HIN * WIN);
    const int t = threadIdx.x;

    u64 wp[11];
#pragma unroll
    for (int k = 0; k < 11; k++) PACK2(wp[k], WG[k], WG[k]);

    // ---- slab load: 2 fields x 42 rows x 11 float4 = 924 tasks ----
#pragma unroll 1
    for (int i = t; i < 2 * SR * 11; i += 256) {
        int fld = i / (SR * 11);
        int s   = i - fld * (SR * 11);
        int r   = s / 11, c = s - r * 11;
        int gy  = y0 + r;     if (gy > HIN - 1) gy = HIN - 1;
        int gx  = x0 + 4 * c; if (gx > WIN - 4) gx = WIN - 4;
        float4 v = *reinterpret_cast<const float4*>((fld ? p2 : p1) + gy * WIN + gx);
        float (*dst)[SRW] = fld ? sb : sa;
        *reinterpret_cast<float4*>(&dst[r][4 * c]) = v;
    }
    __syncthreads();

    // ---- W pass: 42 rows x 8 quads = 336 tasks, 4 x-outputs each ----
#pragma unroll 1
    for (int tt = t; tt < SR * 8; tt += 256) {
        const int row = tt >> 3;
        const int xs  = (tt & 7) * 4;

        float a[16], e[16];
#pragma unroll
        for (int c = 0; c < 4; c++) {
            float4 va = *reinterpret_cast<const float4*>(&sa[row][xs + 4 * c]);
            float4 ve = *reinterpret_cast<const float4*>(&sb[row][xs + 4 * c]);
            a[4*c+0]=va.x; a[4*c+1]=va.y; a[4*c+2]=va.z; a[4*c+3]=va.w;
            e[4*c+0]=ve.x; e[4*c+1]=ve.y; e[4*c+2]=ve.z; e[4*c+3]=ve.w;
        }

        u64 m12[4], s1122[4];
        float s12[4];
#pragma unroll
        for (int j = 0; j < 4; j++) { m12[j] = 0ULL; s1122[j] = 0ULL; s12[j] = 0.f; }

#pragma unroll
        for (int p = 0; p < 14; p++) {
            u64 pv, sq;
            PACK2(pv, a[p], e[p]);
            MUL2(sq, pv, pv);
            float ab = a[p] * e[p];
#pragma unroll
            for (int j = 0; j < 4; j++) {
                int k = p - j;
                if (k >= 0 && k <= 10) {
                    FMA2(m12[j],   wp[k], pv, m12[j]);
                    FMA2(s1122[j], wp[k], sq, s1122[j]);
                    s12[j] = fmaf(WG[k], ab, s12[j]);
                }
            }
        }
        *reinterpret_cast<ulonglong2*>(&wtA[row][xs])     = make_ulonglong2(m12[0], m12[1]);
        *reinterpret_cast<ulonglong2*>(&wtA[row][xs + 2]) = make_ulonglong2(m12[2], m12[3]);
        *reinterpret_cast<ulonglong2*>(&wtB[row][xs])     = make_ulonglong2(s1122[0], s1122[1]);
        *reinterpret_cast<ulonglong2*>(&wtB[row][xs + 2]) = make_ulonglong2(s1122[2], s1122[3]);
        *reinterpret_cast<float4*>(&wtC[row][xs]) = make_float4(s12[0], s12[1], s12[2], s12[3]);
    }
    __syncthreads();

    // ---- H pass: 32 x-cols x 8 y-quads = 256 tasks, 4 y-outputs each ----
    {
        const int x  = t & 31;
        const int ys = (t >> 5) * 4;

        u64 accA[4], accB[4];
        float accC[4];
#pragma unroll
        for (int j = 0; j < 4; j++) { accA[j] = 0ULL; accB[j] = 0ULL; accC[j] = 0.f; }

#pragma unroll
        for (int p = 0; p < 14; p++) {
            u64 vA = wtA[ys + p][x];
            u64 vB = wtB[ys + p][x];
            float vC = wtC[ys + p][x];
#pragma unroll
            for (int j = 0; j < 4; j++) {
                int k = p - j;
                if (k >= 0 && k <= 10) {
                    FMA2(accA[j], wp[k], vA, accA[j]);
                    FMA2(accB[j], wp[k], vB, accB[j]);
                    accC[j] = fmaf(WG[k], vC, accC[j]);
                }
            }
        }

        const int ox = x0 + x;
        if (ox < OW) {
            const size_t rowbase = (size_t)bz * DSTRIDE + (size_t)(y0 + ys) * OWP + ox;
#pragma unroll
            for (int j = 0; j < 4; j++) {
                if (y0 + ys + j < OH) {
                    size_t o = rowbase + (size_t)j * OWP;
                    g_midA[o] = accA[j];
                    g_midB[o] = accB[j];
                    g_midC[o] = accC[j];
                }
            }
        }
    }
}

// ---------------------------------------------------------------------------
// Kernel 2: D-conv + SSIM + reduction. D-split x2 (1456 blocks).
// 13-slot register ring, TWO-iteration load/compute offset, packed FMAs.
// Chunk c: outputs od in [10+59c, 68+59c], slices d0=59c .. d0+68.
// Iteration i: load slice d0+i (slot i%13); compute output d0+i-2 using
// slots (r+1..r+11) mod 13 -> newest consumed value is 2 iterations old.
// ---------------------------------------------------------------------------
__global__ __launch_bounds__(192)
void k_dssim() {
    __shared__ float wsum[6];

    const int by = blockIdx.x;          // b*OH + y
    const int c  = blockIdx.y;          // D-chunk
    const int b  = by / OH;
    const int y  = by - b * OH;
    const int w  = threadIdx.x;         // 0..191
    const bool act = (w < OW);
    const int wl = act ? w : 0;
    const int d0 = c * 59;

    const size_t base = ((size_t)(b * DIN) * OH + y) * OWP + wl;

    u64 wp[11];
#pragma unroll
    for (int k = 0; k < 11; k++) PACK2(wp[k], WG[k], WG[k]);

    u64 hA[13], hB[13];
    float hC[13];
    float part = 0.f;

    for (int i0 = 0; i0 < 78; i0 += 13) {
#pragma unroll
        for (int r = 0; r < 13; r++) {
            const int i = i0 + r;                // ring slot == i % 13 == r
            if (i < 69) {                        // load slice d0+i
                const size_t off = base + (size_t)(d0 + i) * DSTRIDE;
                hA[r] = g_midA[off];
                hB[r] = g_midB[off];
                hC[r] = g_midC[off];
            }
            if (i >= 12 && i <= 70) {            // compute output d0+i-2
                u64 M12 = 0ULL, S1122 = 0ULL;
                float p12 = 0.f;
#pragma unroll
                for (int k = 0; k < 11; k++) {
                    const int s = (r + 1 + k) % 13;   // slice (i-12)+k ; static
                    FMA2(M12,   wp[k], hA[s], M12);
                    FMA2(S1122, wp[k], hB[s], S1122);
                    p12 = fmaf(WG[k], hC[s], p12);
                }
                float m1, m2, p11, p22;
                UNPACK2(m1, m2, M12);
                UNPACK2(p11, p22, S1122);
                float mu11 = m1 * m1;
                float mu22 = m2 * m2;
                float mu12 = m1 * m2;
                float sg1  = p11 - mu11;
                float sg2  = p22 - mu22;
                float sg12 = p12 - mu12;
                const float C1 = 1e-4f;
                const float C2 = 9e-4f;
                float num = (2.f * mu12 + C1) * (2.f * sg12 + C2);
                float den = (mu11 + mu22 + C1) * (sg1 + sg2 + C2);
                if (act) part += __fdividef(num, den);
            }
        }
    }

    float v = part;
#pragma unroll
    for (int o = 16; o > 0; o >>= 1)
        v += __shfl_down_sync(0xffffffffu, v, o);
    if ((threadIdx.x & 31) == 0) wsum[threadIdx.x >> 5] = v;
    __syncthreads();
    if (threadIdx.x == 0) {
        float s = 0.f;
#pragma unroll
        for (int i = 0; i < 6; i++) s += wsum[i];
        g_part[c * NB2 + by] = s;
    }
}

// ---------------------------------------------------------------------------
// Finalize: deterministic double tree over 1456 partials.
// ---------------------------------------------------------------------------
__global__ __launch_bounds__(256)
void k_finalize(float* __restrict__ out) {
    __shared__ double sred[256];
    const int t = threadIdx.x;
    double s = 0.0;
    for (int i = t; i < NBP; i += 256) s += (double)g_part[i];
    sred[t] = s;
    __syncthreads();
    for (int o = 128; o > 0; o >>= 1) {
        if (t < o) sred[t] += sred[t + o];
        __syncthreads();
    }
    if (t == 0) out[0] = (float)(sred[0] / N_OUT);
}

extern "C" void kernel_launch(void* const* d_in, const int* in_sizes, int n_in,
                              void* d_out, int out_size) {
    const float* img1 = (const float*)d_in[0];
    const float* img2 = (const float*)d_in[1];
    float* out = (float*)d_out;

    dim3 g1(GX, GY, BATCH * DIN);   // 6 x 6 x 512 = 18,432 blocks
    k_conv2d<<<g1, 256>>>(img1, img2);
    k_dssim<<<dim3(NB2, 2), 192>>>();
    k_finalize<<<1, 256>>>(out);
}

// round 14
// speedup vs baseline: 1.9389x; 1.1223x over previous
#include <cuda_runtime.h>
#include <cstdint>

typedef unsigned long long u64;

// Problem constants
#define BATCH 4
#define DIN   128
#define HIN   192
#define WIN   192
#define OH    182
#define OW    182
#define OWP   192
#define DSTRIDE   (OH * OWP)                 // 34944
#define MIDF      (BATCH * DIN * DSTRIDE)    // 17,891,328 per field
#define N_OUT     15634528.0                 // 4*118*182*182

// k1 tile: 32x32 outputs
#define TY 32
#define TX 32
#define SR 42        // TY + 10 wt rows
#define WTW 36       // wt row stride
#define GX 6         // ceil(182/32)
#define GY 6

#define NB2 (BATCH * OH)                     // 728
#define NBP (NB2 * 2)                        // 1456 partials (D-split x2)

// Gaussian(sigma=1.5, K=11)
__device__ constexpr float WG[11] = {
    0.00102834f, 0.00759875f, 0.03600077f, 0.10936078f, 0.21300553f,
    0.26601172f,
    0.21300553f, 0.10936078f, 0.03600077f, 0.00759875f, 0.00102834f
};

// ---- packed f32x2 helpers (Blackwell FFMA2 via PTX) ----
#define FMA2(d, a, b, c) asm("fma.rn.f32x2 %0, %1, %2, %3;" : "=l"(d) : "l"(a), "l"(b), "l"(c))
#define MUL2(d, a, b)    asm("mul.rn.f32x2 %0, %1, %2;"      : "=l"(d) : "l"(a), "l"(b))
#define PACK2(d, lo, hi) asm("mov.b64 %0, {%1, %2};"         : "=l"(d) : "f"(lo), "f"(hi))
#define UNPACK2(lo, hi, v) asm("mov.b64 {%0, %1}, %2;"       : "=f"(lo), "=f"(hi) : "l"(v))

// Scratch: A=(mu1,mu2) f32x2, B=(s11,s22) f32x2, C=s12 f32.  ~358 MB total.
__device__ u64   g_midA[MIDF];
__device__ u64   g_midB[MIDF];
__device__ float g_midC[MIDF];
__device__ float g_part[NBP];

// W-pass worker: one task = 4 consecutive x-outputs on one wt row.
__device__ __forceinline__ void w_task(
    const float* __restrict__ p1, const float* __restrict__ p2,
    int y0, int x0, int row, int xs,
    const u64* wp,
    u64 (*wtA)[WTW], u64 (*wtB)[WTW], float (*wtC)[WTW])
{
    int gy = y0 + row; if (gy > HIN - 1) gy = HIN - 1;
    const float* r1 = p1 + gy * WIN;
    const float* r2 = p2 + gy * WIN;

    float a[16], e[16];
#pragma unroll
    for (int c = 0; c < 4; c++) {
        int gx = x0 + xs + 4 * c; if (gx > WIN - 4) gx = WIN - 4;
        float4 va = *reinterpret_cast<const float4*>(r1 + gx);
        float4 ve = *reinterpret_cast<const float4*>(r2 + gx);
        a[4*c+0]=va.x; a[4*c+1]=va.y; a[4*c+2]=va.z; a[4*c+3]=va.w;
        e[4*c+0]=ve.x; e[4*c+1]=ve.y; e[4*c+2]=ve.z; e[4*c+3]=ve.w;
    }

    u64 m12[4], s1122[4];
    float s12[4];
#pragma unroll
    for (int j = 0; j < 4; j++) { m12[j] = 0ULL; s1122[j] = 0ULL; s12[j] = 0.f; }

#pragma unroll
    for (int p = 0; p < 14; p++) {
        u64 pv, sq;
        PACK2(pv, a[p], e[p]);
        MUL2(sq, pv, pv);
        float ab = a[p] * e[p];
#pragma unroll
        for (int j = 0; j < 4; j++) {
            int k = p - j;
            if (k >= 0 && k <= 10) {
                FMA2(m12[j],   wp[k], pv, m12[j]);
                FMA2(s1122[j], wp[k], sq, s1122[j]);
                s12[j] = fmaf(WG[k], ab, s12[j]);
            }
        }
    }
    *reinterpret_cast<ulonglong2*>(&wtA[row][xs])     = make_ulonglong2(m12[0], m12[1]);
    *reinterpret_cast<ulonglong2*>(&wtA[row][xs + 2]) = make_ulonglong2(m12[2], m12[3]);
    *reinterpret_cast<ulonglong2*>(&wtB[row][xs])     = make_ulonglong2(s1122[0], s1122[1]);
    *reinterpret_cast<ulonglong2*>(&wtB[row][xs + 2]) = make_ulonglong2(s1122[2], s1122[3]);
    *reinterpret_cast<float4*>(&wtC[row][xs]) = make_float4(s12[0], s12[1], s12[2], s12[3]);
}

// ---------------------------------------------------------------------------
// Kernel 1: per depth slice, separable 2D Gaussian over packed fields.
// NO input slab: W-pass reads its 16-float windows directly from global
// (L2 absorbs the 3x intra-tile overlap; ~44KB/block less L1 traffic and
// one barrier fewer). W-pass: 336 tasks (256 + 80). H-pass: 128 tasks x 8 y.
// ---------------------------------------------------------------------------
__global__ __launch_bounds__(256, 4)
void k_conv2d(const float* __restrict__ img1, const float* __restrict__ img2) {
    __shared__ u64   wtA[SR][WTW];
    __shared__ u64   wtB[SR][WTW];
    __shared__ float wtC[SR][WTW];

    const int bz = blockIdx.z;
    const int y0 = blockIdx.y * TY;
    const int x0 = blockIdx.x * TX;
    const float* p1 = img1 + (size_t)bz * (HIN * WIN);
    const float* p2 = img2 + (size_t)bz * (HIN * WIN);
    const int t = threadIdx.x;

    u64 wp[11];
#pragma unroll
    for (int k = 0; k < 11; k++) PACK2(wp[k], WG[k], WG[k]);

    // ---- W pass: 336 tasks = 256 (all threads) + 80 (threads 0..79) ----
    w_task(p1, p2, y0, x0, t >> 3, (t & 7) * 4, wp, wtA, wtB, wtC);
    if (t < 80) {
        const int tt = t + 256;
        w_task(p1, p2, y0, x0, tt >> 3, (tt & 7) * 4, wp, wtA, wtB, wtC);
    }
    __syncthreads();

    // ---- H pass: 32 x-cols x 4 y-octs = 128 tasks, 8 y-outputs each ----
    if (t < 128) {
        const int x  = t & 31;
        const int ys = (t >> 5) * 8;

        u64 accA[8], accB[8];
        float accC[8];
#pragma unroll
        for (int j = 0; j < 8; j++) { accA[j] = 0ULL; accB[j] = 0ULL; accC[j] = 0.f; }

#pragma unroll
        for (int p = 0; p < 18; p++) {
            u64 vA = wtA[ys + p][x];
            u64 vB = wtB[ys + p][x];
            float vC = wtC[ys + p][x];
#pragma unroll
            for (int j = 0; j < 8; j++) {
                int k = p - j;
                if (k >= 0 && k <= 10) {
                    FMA2(accA[j], wp[k], vA, accA[j]);
                    FMA2(accB[j], wp[k], vB, accB[j]);
                    accC[j] = fmaf(WG[k], vC, accC[j]);
                }
            }
        }

        const int ox = x0 + x;
        if (ox < OW) {
            // number of valid y outputs in this oct (y0+ys..y0+ys+7 vs OH)
            int ny = OH - (y0 + ys);
            if (ny > 8) ny = 8;
            const size_t rowbase = (size_t)bz * DSTRIDE + (size_t)(y0 + ys) * OWP + ox;
#pragma unroll
            for (int j = 0; j < 8; j++) {
                if (j < ny) {
                    size_t o = rowbase + (size_t)j * OWP;
                    g_midA[o] = accA[j];
                    g_midB[o] = accB[j];
                    g_midC[o] = accC[j];
                }
            }
        }
    }
}

// ---------------------------------------------------------------------------
// Kernel 2: D-conv + SSIM + reduction. D-split x2 (1456 blocks).
// 13-slot register ring, two-iteration load/compute offset, packed FMAs.
// (Frozen for attribution.)
// ---------------------------------------------------------------------------
__global__ __launch_bounds__(192)
void k_dssim() {
    __shared__ float wsum[6];

    const int by = blockIdx.x;          // b*OH + y
    const int c  = blockIdx.y;          // D-chunk
    const int b  = by / OH;
    const int y  = by - b * OH;
    const int w  = threadIdx.x;         // 0..191
    const bool act = (w < OW);
    const int wl = act ? w : 0;
    const int d0 = c * 59;

    const size_t base = ((size_t)(b * DIN) * OH + y) * OWP + wl;

    u64 wp[11];
#pragma unroll
    for (int k = 0; k < 11; k++) PACK2(wp[k], WG[k], WG[k]);

    u64 hA[13], hB[13];
    float hC[13];
    float part = 0.f;

    for (int i0 = 0; i0 < 78; i0 += 13) {
#pragma unroll
        for (int r = 0; r < 13; r++) {
            const int i = i0 + r;                // ring slot == i % 13 == r
            if (i < 69) {                        // load slice d0+i
                const size_t off = base + (size_t)(d0 + i) * DSTRIDE;
                hA[r] = g_midA[off];
                hB[r] = g_midB[off];
                hC[r] = g_midC[off];
            }
            if (i >= 12 && i <= 70) {            // compute output d0+i-2
                u64 M12 = 0ULL, S1122 = 0ULL;
                float p12 = 0.f;
#pragma unroll
                for (int k = 0; k < 11; k++) {
                    const int s = (r + 1 + k) % 13;   // slice (i-12)+k ; static
                    FMA2(M12,   wp[k], hA[s], M12);
                    FMA2(S1122, wp[k], hB[s], S1122);
                    p12 = fmaf(WG[k], hC[s], p12);
                }
                float m1, m2, p11, p22;
                UNPACK2(m1, m2, M12);
                UNPACK2(p11, p22, S1122);
                float mu11 = m1 * m1;
                float mu22 = m2 * m2;
                float mu12 = m1 * m2;
                float sg1  = p11 - mu11;
                float sg2  = p22 - mu22;
                float sg12 = p12 - mu12;
                const float C1 = 1e-4f;
                const float C2 = 9e-4f;
                float num = (2.f * mu12 + C1) * (2.f * sg12 + C2);
                float den = (mu11 + mu22 + C1) * (sg1 + sg2 + C2);
                if (act) part += __fdividef(num, den);
            }
        }
    }

    float v = part;
#pragma unroll
    for (int o = 16; o > 0; o >>= 1)
        v += __shfl_down_sync(0xffffffffu, v, o);
    if ((threadIdx.x & 31) == 0) wsum[threadIdx.x >> 5] = v;
    __syncthreads();
    if (threadIdx.x == 0) {
        float s = 0.f;
#pragma unroll
        for (int i = 0; i < 6; i++) s += wsum[i];
        g_part[c * NB2 + by] = s;
    }
}

// ---------------------------------------------------------------------------
// Finalize: deterministic double tree over 1456 partials.
// ---------------------------------------------------------------------------
__global__ __launch_bounds__(256)
void k_finalize(float* __restrict__ out) {
    __shared__ double sred[256];
    const int t = threadIdx.x;
    double s = 0.0;
    for (int i = t; i < NBP; i += 256) s += (double)g_part[i];
    sred[t] = s;
    __syncthreads();
    for (int o = 128; o > 0; o >>= 1) {
        if (t < o) sred[t] += sred[t + o];
        __syncthreads();
    }
    if (t == 0) out[0] = (float)(sred[0] / N_OUT);
}

extern "C" void kernel_launch(void* const* d_in, const int* in_sizes, int n_in,
                              void* d_out, int out_size) {
    const float* img1 = (const float*)d_in[0];
    const float* img2 = (const float*)d_in[1];
    float* out = (float*)d_out;

    dim3 g1(GX, GY, BATCH * DIN);   // 6 x 6 x 512 = 18,432 blocks
    k_conv2d<<<g1, 256>>>(img1, img2);
    k_dssim<<<dim3(NB2, 2), 192>>>();
    k_finalize<<<1, 256>>>(out);
}

// round 17
// speedup vs baseline: 1.9536x; 1.0076x over previous
#include <cuda_runtime.h>
#include <cstdint>

typedef unsigned long long u64;

// Problem constants
#define BATCH 4
#define DIN   128
#define HIN   192
#define WIN   192
#define OH    182
#define OW    182
#define OWP   192
#define DSTRIDE   (OH * OWP)                 // 34944
#define MIDF      (BATCH * DIN * DSTRIDE)    // 17,891,328 per field
#define N_OUT     15634528.0                 // 4*118*182*182

// k1 tile: 32x32 outputs
#define TY 32
#define TX 32
#define SR 42        // TY + 10 wt rows
#define WTW 36       // wt row stride
#define GX 6         // ceil(182/32)
#define GY 6

#define NB2 (BATCH * OH)                     // 728
#define NBP (NB2 * 2)                        // 1456 partials (D-split x2)

// Gaussian(sigma=1.5, K=11)
__device__ constexpr float WG[11] = {
    0.00102834f, 0.00759875f, 0.03600077f, 0.10936078f, 0.21300553f,
    0.26601172f,
    0.21300553f, 0.10936078f, 0.03600077f, 0.00759875f, 0.00102834f
};

// ---- packed f32x2 helpers (Blackwell FFMA2 via PTX) ----
#define FMA2(d, a, b, c) asm("fma.rn.f32x2 %0, %1, %2, %3;" : "=l"(d) : "l"(a), "l"(b), "l"(c))
#define MUL2(d, a, b)    asm("mul.rn.f32x2 %0, %1, %2;"      : "=l"(d) : "l"(a), "l"(b))
#define ADD2(d, a, b)    asm("add.rn.f32x2 %0, %1, %2;"      : "=l"(d) : "l"(a), "l"(b))
#define PACK2(d, lo, hi) asm("mov.b64 %0, {%1, %2};"         : "=l"(d) : "f"(lo), "f"(hi))
#define UNPACK2(lo, hi, v) asm("mov.b64 {%0, %1}, %2;"       : "=f"(lo), "=f"(hi) : "l"(v))

// Scratch: A=(mu1,mu2) f32x2, B=(s11,s22) f32x2, C=s12 f32.  ~358 MB total.
__device__ u64   g_midA[MIDF];
__device__ u64   g_midB[MIDF];
__device__ float g_midC[MIDF];
__device__ float g_part[NBP];

// W-pass worker: one task = 4 consecutive x-outputs on one wt row.
__device__ __forceinline__ void w_task(
    const float* __restrict__ p1, const float* __restrict__ p2,
    int y0, int x0, int row, int xs,
    const u64* wp,
    u64 (*wtA)[WTW], u64 (*wtB)[WTW], float (*wtC)[WTW])
{
    int gy = y0 + row; if (gy > HIN - 1) gy = HIN - 1;
    const float* r1 = p1 + gy * WIN;
    const float* r2 = p2 + gy * WIN;

    float a[16], e[16];
#pragma unroll
    for (int c = 0; c < 4; c++) {
        int gx = x0 + xs + 4 * c; if (gx > WIN - 4) gx = WIN - 4;
        float4 va = *reinterpret_cast<const float4*>(r1 + gx);
        float4 ve = *reinterpret_cast<const float4*>(r2 + gx);
        a[4*c+0]=va.x; a[4*c+1]=va.y; a[4*c+2]=va.z; a[4*c+3]=va.w;
        e[4*c+0]=ve.x; e[4*c+1]=ve.y; e[4*c+2]=ve.z; e[4*c+3]=ve.w;
    }

    u64 m12[4], s1122[4];
    float s12[4];
#pragma unroll
    for (int j = 0; j < 4; j++) { m12[j] = 0ULL; s1122[j] = 0ULL; s12[j] = 0.f; }

#pragma unroll
    for (int p = 0; p < 14; p++) {
        u64 pv, sq;
        PACK2(pv, a[p], e[p]);
        MUL2(sq, pv, pv);
        float ab = a[p] * e[p];
#pragma unroll
        for (int j = 0; j < 4; j++) {
            int k = p - j;
            if (k >= 0 && k <= 10) {
                FMA2(m12[j],   wp[k], pv, m12[j]);
                FMA2(s1122[j], wp[k], sq, s1122[j]);
                s12[j] = fmaf(WG[k], ab, s12[j]);
            }
        }
    }
    *reinterpret_cast<ulonglong2*>(&wtA[row][xs])     = make_ulonglong2(m12[0], m12[1]);
    *reinterpret_cast<ulonglong2*>(&wtA[row][xs + 2]) = make_ulonglong2(m12[2], m12[3]);
    *reinterpret_cast<ulonglong2*>(&wtB[row][xs])     = make_ulonglong2(s1122[0], s1122[1]);
    *reinterpret_cast<ulonglong2*>(&wtB[row][xs + 2]) = make_ulonglong2(s1122[2], s1122[3]);
    *reinterpret_cast<float4*>(&wtC[row][xs]) = make_float4(s12[0], s12[1], s12[2], s12[3]);
}

// ---------------------------------------------------------------------------
// Kernel 1: per depth slice, separable 2D Gaussian over packed fields.
// (Byte-identical to the 268us passing version.)
// ---------------------------------------------------------------------------
__global__ __launch_bounds__(256, 4)
void k_conv2d(const float* __restrict__ img1, const float* __restrict__ img2) {
    __shared__ u64   wtA[SR][WTW];
    __shared__ u64   wtB[SR][WTW];
    __shared__ float wtC[SR][WTW];

    const int bz = blockIdx.z;
    const int y0 = blockIdx.y * TY;
    const int x0 = blockIdx.x * TX;
    const float* p1 = img1 + (size_t)bz * (HIN * WIN);
    const float* p2 = img2 + (size_t)bz * (HIN * WIN);
    const int t = threadIdx.x;

    u64 wp[11];
#pragma unroll
    for (int k = 0; k < 11; k++) PACK2(wp[k], WG[k], WG[k]);

    // ---- W pass: 336 tasks = 256 (all threads) + 80 (threads 0..79) ----
    w_task(p1, p2, y0, x0, t >> 3, (t & 7) * 4, wp, wtA, wtB, wtC);
    if (t < 80) {
        const int tt = t + 256;
        w_task(p1, p2, y0, x0, tt >> 3, (tt & 7) * 4, wp, wtA, wtB, wtC);
    }
    __syncthreads();

    // ---- H pass: 32 x-cols x 4 y-octs = 128 tasks, 8 y-outputs each ----
    if (t < 128) {
        const int x  = t & 31;
        const int ys = (t >> 5) * 8;

        u64 accA[8], accB[8];
        float accC[8];
#pragma unroll
        for (int j = 0; j < 8; j++) { accA[j] = 0ULL; accB[j] = 0ULL; accC[j] = 0.f; }

#pragma unroll
        for (int p = 0; p < 18; p++) {
            u64 vA = wtA[ys + p][x];
            u64 vB = wtB[ys + p][x];
            float vC = wtC[ys + p][x];
#pragma unroll
            for (int j = 0; j < 8; j++) {
                int k = p - j;
                if (k >= 0 && k <= 10) {
                    FMA2(accA[j], wp[k], vA, accA[j]);
                    FMA2(accB[j], wp[k], vB, accB[j]);
                    accC[j] = fmaf(WG[k], vC, accC[j]);
                }
            }
        }

        const int ox = x0 + x;
        if (ox < OW) {
            int ny = OH - (y0 + ys);
            if (ny > 8) ny = 8;
            const size_t rowbase = (size_t)bz * DSTRIDE + (size_t)(y0 + ys) * OWP + ox;
#pragma unroll
            for (int j = 0; j < 8; j++) {
                if (j < ny) {
                    size_t o = rowbase + (size_t)j * OWP;
                    g_midA[o] = accA[j];
                    g_midB[o] = accB[j];
                    g_midC[o] = accC[j];
                }
            }
        }
    }
}

// ---------------------------------------------------------------------------
// Kernel 2: D-conv + SSIM + reduction. D-split x2 (1456 blocks).
// 13-slot register ring, two-iteration load/compute offset.
// Even/odd-tap split as TWO STRAIGHT-LINE LOOPS (no conditional in body):
// 6 independent FMA chains of depth <=6 instead of 3 chains of depth 11.
// ---------------------------------------------------------------------------
__global__ __launch_bounds__(192)
void k_dssim() {
    __shared__ float wsum[6];

    const int by = blockIdx.x;          // b*OH + y
    const int c  = blockIdx.y;          // D-chunk
    const int b  = by / OH;
    const int y  = by - b * OH;
    const int w  = threadIdx.x;         // 0..191
    const bool act = (w < OW);
    const int wl = act ? w : 0;
    const int d0 = c * 59;

    const size_t base = ((size_t)(b * DIN) * OH + y) * OWP + wl;

    u64 wp[11];
#pragma unroll
    for (int k = 0; k < 11; k++) PACK2(wp[k], WG[k], WG[k]);

    u64 hA[13], hB[13];
    float hC[13];
    float part = 0.f;

    for (int i0 = 0; i0 < 78; i0 += 13) {
#pragma unroll
        for (int r = 0; r < 13; r++) {
            const int i = i0 + r;                // ring slot == i % 13 == r
            if (i < 69) {                        // load slice d0+i
                const size_t off = base + (size_t)(d0 + i) * DSTRIDE;
                hA[r] = g_midA[off];
                hB[r] = g_midB[off];
                hC[r] = g_midC[off];
            }
            if (i >= 12 && i <= 70) {            // compute output d0+i-2
                u64 Me = 0ULL, Mo = 0ULL, Se = 0ULL, So = 0ULL;
                float pe = 0.f, po = 0.f;
                // even taps: k = 0,2,4,6,8,10  (6 taps, chain depth 6)
#pragma unroll
                for (int q = 0; q < 6; q++) {
                    const int k = 2 * q;
                    const int s = (r + 1 + k) % 13;   // static after unroll
                    FMA2(Me, wp[k], hA[s], Me);
                    FMA2(Se, wp[k], hB[s], Se);
                    pe = fmaf(WG[k], hC[s], pe);
                }
                // odd taps: k = 1,3,5,7,9  (5 taps, chain depth 5)
#pragma unroll
                for (int q = 0; q < 5; q++) {
                    const int k = 2 * q + 1;
                    const int s = (r + 1 + k) % 13;   // static after unroll
                    FMA2(Mo, wp[k], hA[s], Mo);
                    FMA2(So, wp[k], hB[s], So);
                    po = fmaf(WG[k], hC[s], po);
                }
                u64 M12, S1122;
                ADD2(M12, Me, Mo);
                ADD2(S1122, Se, So);
                float p12 = pe + po;

                float m1, m2, p11, p22;
                UNPACK2(m1, m2, M12);
                UNPACK2(p11, p22, S1122);
                float mu11 = m1 * m1;
                float mu22 = m2 * m2;
                float mu12 = m1 * m2;
                float sg1  = p11 - mu11;
                float sg2  = p22 - mu22;
                float sg12 = p12 - mu12;
                const float C1 = 1e-4f;
                const float C2 = 9e-4f;
                float num = (2.f * mu12 + C1) * (2.f * sg12 + C2);
                float den = (mu11 + mu22 + C1) * (sg1 + sg2 + C2);
                if (act) part += __fdividef(num, den);
            }
        }
    }

    float v = part;
#pragma unroll
    for (int o = 16; o > 0; o >>= 1)
        v += __shfl_down_sync(0xffffffffu, v, o);
    if ((threadIdx.x & 31) == 0) wsum[threadIdx.x >> 5] = v;
    __syncthreads();
    if (threadIdx.x == 0) {
        float s = 0.f;
#pragma unroll
        for (int i = 0; i < 6; i++) s += wsum[i];
        g_part[c * NB2 + by] = s;
    }
}

// ---------------------------------------------------------------------------
// Finalize: deterministic double tree over 1456 partials.
// ---------------------------------------------------------------------------
__global__ __launch_bounds__(256)
void k_finalize(float* __restrict__ out) {
    __shared__ double sred[256];
    const int t = threadIdx.x;
    double s = 0.0;
    for (int i = t; i < NBP; i += 256) s += (double)g_part[i];
    sred[t] = s;
    __syncthreads();
    for (int o = 128; o > 0; o >>= 1) {
        if (t < o) sred[t] += sred[t + o];
        __syncthreads();
    }
    if (t == 0) out[0] = (float)(sred[0] / N_OUT);
}

extern "C" void kernel_launch(void* const* d_in, const int* in_sizes, int n_in,
                              void* d_out, int out_size) {
    const float* img1 = (const float*)d_in[0];
    const float* img2 = (const float*)d_in[1];
    float* out = (float*)d_out;

    dim3 g1(GX, GY, BATCH * DIN);   // 6 x 6 x 512 = 18,432 blocks
    k_conv2d<<<g1, 256>>>(img1, img2);
    k_dssim<<<dim3(NB2, 2), 192>>>();
    k_finalize<<<1, 256>>>(out);
}